// round 12
// baseline (speedup 1.0000x reference)
#include <cuda_runtime.h>
#include <cuda_bf16.h>
#include <cstdint>

// ---------------------------------------------------------------------------
// DigitConvolutionalModel via warp-level mma.sync (bf16 split hi/lo, fp32
// accum). R12: pass-outer MMA ordering — consecutive MMAs hit distinct
// accumulators, breaking the 3-deep HMMA RAW chains that capped tensor at 58%.
//   conv_split: conv3x3 -> h0 hi/lo bf16 [B][704]
//   wprep:      split fc1_w (pad 676->704) and fc2_w into hi/lo bf16
//   out_init:   out[b][o] = out_b[o]
//   gemm<0>:    h1 = relu(h0 @ w1^T + b1) -> split bf16 h1 hi/lo
//   gemm<1>:    h2 = relu(h1 @ w2^T + b2); out += h2-slice @ out_w^T (fused)
// ---------------------------------------------------------------------------

#define BROWS  32768
#define K1RAW  676
#define K1PAD  704          // 22 * 32
#define K2     512
#define NHID   512
#define NOUT   10
#define CTHR   256

#define BM 128
#define BN 128
#define BK 32
#define GTHR 256            // 8 warps: 4 (m) x 2 (n); warp tile 32 x 64

// dynamic smem layout (u32 units)
#define ST_A_H   0
#define ST_A_L   2560
#define ST_B_H   5120
#define ST_B_L   7680
#define ST_SIZE  10240              // one stage = 40960 B
#define ST_BIAS  (2 * ST_SIZE)      // float[128]
#define ST_OUTW  (ST_BIAS + 128)    // float[10][128]
#define DSMEM_BYTES ((2 * ST_SIZE + 128 + 1280) * 4 + 256)

// ---- scratch ---------------------------------------------------------------
__device__ __align__(16) __nv_bfloat16 g_h0h[(size_t)BROWS * K1PAD];
__device__ __align__(16) __nv_bfloat16 g_h0l[(size_t)BROWS * K1PAD];
__device__ __align__(16) __nv_bfloat16 g_w1h[(size_t)NHID * K1PAD];
__device__ __align__(16) __nv_bfloat16 g_w1l[(size_t)NHID * K1PAD];
__device__ __align__(16) __nv_bfloat16 g_w2h[(size_t)NHID * K2];
__device__ __align__(16) __nv_bfloat16 g_w2l[(size_t)NHID * K2];
__device__ __align__(16) __nv_bfloat16 g_h1h[(size_t)BROWS * K2];
__device__ __align__(16) __nv_bfloat16 g_h1l[(size_t)BROWS * K2];

// ---- helpers ---------------------------------------------------------------
__device__ __forceinline__ void split_bf16(float x, __nv_bfloat16& h,
                                           __nv_bfloat16& l) {
    h = __float2bfloat16(x);
    l = __float2bfloat16(x - __bfloat162float(h));
}
__device__ __forceinline__ uint32_t pack_split_hi(float a, float b,
                                                  uint32_t& lo_pack) {
    __nv_bfloat16 ha, la, hb, lb;
    split_bf16(a, ha, la);
    split_bf16(b, hb, lb);
    lo_pack = (uint32_t)__bfloat16_as_ushort(la) |
              ((uint32_t)__bfloat16_as_ushort(lb) << 16);
    return (uint32_t)__bfloat16_as_ushort(ha) |
           ((uint32_t)__bfloat16_as_ushort(hb) << 16);
}

__device__ __forceinline__ void mma16816(float* c, const uint32_t* a,
                                         const uint32_t* b) {
    asm volatile(
        "mma.sync.aligned.m16n8k16.row.col.f32.bf16.bf16.f32 "
        "{%0,%1,%2,%3}, {%4,%5,%6,%7}, {%8,%9}, {%0,%1,%2,%3};"
        : "+f"(c[0]), "+f"(c[1]), "+f"(c[2]), "+f"(c[3])
        : "r"(a[0]), "r"(a[1]), "r"(a[2]), "r"(a[3]), "r"(b[0]), "r"(b[1]));
}
#define LDSM4(r, addr) \
    asm volatile("ldmatrix.sync.aligned.m8n8.x4.shared.b16 {%0,%1,%2,%3}, [%4];" \
        : "=r"((r)[0]), "=r"((r)[1]), "=r"((r)[2]), "=r"((r)[3]) : "r"(addr))
__device__ __forceinline__ void cp16(uint32_t saddr, const void* gaddr) {
    asm volatile("cp.async.cg.shared.global [%0], [%1], 16;"
                 :: "r"(saddr), "l"(gaddr));
}
#define CP_COMMIT() asm volatile("cp.async.commit_group;" ::: "memory")
#define CP_WAIT(n)  asm volatile("cp.async.wait_group %0;" :: "n"(n) : "memory")

// ---------------------------------------------------------------------------
// conv + split, packed u32 writes (2 outputs / thread)
// ---------------------------------------------------------------------------
__global__ void conv_split_kernel(const float* __restrict__ x,
                                  const float* __restrict__ w) {
    __shared__ float sw[9];
    int tid = threadIdx.x;
    if (tid < 9) sw[tid] = w[tid];
    __syncthreads();

    size_t idx = (size_t)blockIdx.x * blockDim.x + tid;
    if (idx >= (size_t)BROWS * (K1PAD / 2)) return;
    int b = (int)(idx / (K1PAD / 2));
    int pp = (int)(idx - (size_t)b * (K1PAD / 2));
    int p0 = pp * 2;

    float s[2] = {0.0f, 0.0f};
#pragma unroll
    for (int u = 0; u < 2; u++) {
        int p = p0 + u;
        if (p < K1RAW) {
            int i = p / 26, j = p - i * 26;
            const float* xb = x + (size_t)b * 784 + i * 28 + j;
            float acc = 0.0f;
#pragma unroll
            for (int di = 0; di < 3; di++)
#pragma unroll
                for (int dj = 0; dj < 3; dj++)
                    acc = fmaf(xb[di * 28 + dj], sw[di * 3 + dj], acc);
            s[u] = acc;
        }
    }
    uint32_t lo;
    uint32_t hi = pack_split_hi(s[0], s[1], lo);
    ((uint32_t*)g_h0h)[idx] = hi;
    ((uint32_t*)g_h0l)[idx] = lo;
}

// ---------------------------------------------------------------------------
// weight split prep
// ---------------------------------------------------------------------------
__global__ void wprep_kernel(const float* __restrict__ w1,
                             const float* __restrict__ w2) {
    int idx = blockIdx.x * blockDim.x + threadIdx.x;
    int n1 = NHID * K1PAD;
    if (idx < n1) {
        int n = idx / K1PAD, k = idx - n * K1PAD;
        float v = (k < K1RAW) ? w1[n * K1RAW + k] : 0.0f;
        __nv_bfloat16 h, l;
        split_bf16(v, h, l);
        g_w1h[idx] = h;
        g_w1l[idx] = l;
    } else {
        int j = idx - n1;
        if (j < NHID * K2) {
            float v = w2[j];
            __nv_bfloat16 h, l;
            split_bf16(v, h, l);
            g_w2h[j] = h;
            g_w2l[j] = l;
        }
    }
}

// ---------------------------------------------------------------------------
// out init: out[b][o] = out_b[o]
// ---------------------------------------------------------------------------
__global__ void out_init_kernel(const float* __restrict__ out_b,
                                float* __restrict__ out) {
    int idx = blockIdx.x * blockDim.x + threadIdx.x;
    if (idx < BROWS * NOUT) out[idx] = out_b[idx % NOUT];
}

// ---------------------------------------------------------------------------
// Tiled GEMM, split-bf16 3-pass (pass-outer MMA order).
// MODE 0: out = relu(C + bias) split -> (outH, outL) bf16
// MODE 1: v = relu(C + bias); atomicAdd partial v @ out_w^T into outO
// ---------------------------------------------------------------------------
template <int MODE>
__global__ void __launch_bounds__(GTHR, 2)
gemm_kernel(const __nv_bfloat16* __restrict__ Ah,
            const __nv_bfloat16* __restrict__ Al,
            const __nv_bfloat16* __restrict__ Wh,
            const __nv_bfloat16* __restrict__ Wl,
            const float* __restrict__ bias, int K,
            __nv_bfloat16* __restrict__ outH,
            __nv_bfloat16* __restrict__ outL,
            const float* __restrict__ outW,
            float* __restrict__ outO) {
    extern __shared__ uint32_t dsm[];
    float* sBias = (float*)(dsm + ST_BIAS);
    float* sOutW = (float*)(dsm + ST_OUTW);
    const uint32_t sbase = (uint32_t)__cvta_generic_to_shared(dsm);

    const int tid = threadIdx.x;
    const int lane = tid & 31;
    const int warp = tid >> 5;
    const int wm = warp & 3;
    const int wn = warp >> 2;
    const size_t rowA0 = (size_t)blockIdx.y * BM;
    const int ncol0 = blockIdx.x * BN;

    if (tid < BN) sBias[tid] = bias[ncol0 + tid];
    if (MODE == 1) {
        for (int i = tid; i < NOUT * BN; i += GTHR) {
            int o = i >> 7, j = i & 127;
            sOutW[o * BN + j] = outW[o * NHID + ncol0 + j];
        }
    }

    float c[2][8][4];
#pragma unroll
    for (int mt = 0; mt < 2; mt++)
#pragma unroll
        for (int nt = 0; nt < 8; nt++)
#pragma unroll
            for (int i = 0; i < 4; i++) c[mt][nt][i] = 0.0f;

    const int kcn = K / BK;

    auto stage = [&](int kc, int s) {
        uint32_t sb = sbase + (uint32_t)(s * ST_SIZE * 4);
#pragma unroll
        for (int it = 0; it < 2; it++) {
            int i = tid + it * GTHR;
            int row = i >> 2, quad = i & 3;
            uint32_t soff = (uint32_t)(row * 80 + quad * 16);
            size_t ga = (rowA0 + row) * (size_t)K + kc * BK + quad * 8;
            size_t gb = (size_t)(ncol0 + row) * K + kc * BK + quad * 8;
            cp16(sb + ST_A_H * 4 + soff, Ah + ga);
            cp16(sb + ST_A_L * 4 + soff, Al + ga);
            cp16(sb + ST_B_H * 4 + soff, Wh + gb);
            cp16(sb + ST_B_L * 4 + soff, Wl + gb);
        }
    };

    stage(0, 0);
    CP_COMMIT();

    const int g = lane >> 3, lr8 = lane & 7;
    const int arsel = (g & 1) ? 8 : 0;
    const int absel = (g & 2) ? 16 : 0;
    const int brsel = (g & 2) ? 8 : 0;
    const int bbsel = (g & 1) ? 16 : 0;

    for (int kc = 0; kc < kcn; kc++) {
        if (kc + 1 < kcn) {
            stage(kc + 1, (kc + 1) & 1);
            CP_COMMIT();
            CP_WAIT(1);
        } else {
            CP_WAIT(0);
        }
        __syncthreads();

        const uint32_t sb = sbase + (uint32_t)((kc & 1) * ST_SIZE * 4);
        const uint32_t aAh = sb + ST_A_H * 4;
        const uint32_t aAl = sb + ST_A_L * 4;
        const uint32_t aBh = sb + ST_B_H * 4;
        const uint32_t aBl = sb + ST_B_L * 4;

#pragma unroll
        for (int ks = 0; ks < 2; ks++) {
            uint32_t ah[2][4], al[2][4];
#pragma unroll
            for (int mt = 0; mt < 2; mt++) {
                int r = wm * 32 + mt * 16 + lr8 + arsel;
                uint32_t off = (uint32_t)(r * 80 + ks * 32 + absel);
                LDSM4(ah[mt], aAh + off);
                LDSM4(al[mt], aAl + off);
            }
            uint32_t bhq[2][4], blq[2][4];
            {
                int nr = wn * 64 + lr8 + brsel;
                uint32_t off = (uint32_t)(nr * 80 + ks * 32 + bbsel);
                LDSM4(bhq[0], aBh + off);
                LDSM4(blq[0], aBl + off);
            }
#pragma unroll
            for (int np = 0; np < 4; np++) {
                const int cur = np & 1;
                if (np < 3) {
                    int nr = wn * 64 + (np + 1) * 16 + lr8 + brsel;
                    uint32_t off = (uint32_t)(nr * 80 + ks * 32 + bbsel);
                    LDSM4(bhq[cur ^ 1], aBh + off);
                    LDSM4(blq[cur ^ 1], aBl + off);
                }
                // pass-outer order: consecutive MMAs hit distinct accumulators;
                // same-c dependencies are 4 apart. Per-c summation order is
                // unchanged (hh, hl, lh) -> bit-identical results.
#pragma unroll
                for (int pass = 0; pass < 3; pass++) {
#pragma unroll
                    for (int hf = 0; hf < 2; hf++) {
                        int nt = np * 2 + hf;
                        const uint32_t* bf =
                            (pass == 1) ? (blq[cur] + 2 * hf) : (bhq[cur] + 2 * hf);
#pragma unroll
                        for (int mt = 0; mt < 2; mt++) {
                            const uint32_t* af = (pass == 2) ? al[mt] : ah[mt];
                            mma16816(c[mt][nt], af, bf);
                        }
                    }
                }
            }
        }
        __syncthreads();
    }

    // epilogue
    const int lq = lane >> 2;
    const int lr = lane & 3;
#pragma unroll
    for (int mt = 0; mt < 2; mt++) {
        size_t r0 = rowA0 + wm * 32 + mt * 16 + lq;
        size_t r1 = r0 + 8;
        float p0[NOUT], p1[NOUT];
        if (MODE == 1) {
#pragma unroll
            for (int o = 0; o < NOUT; o++) { p0[o] = 0.0f; p1[o] = 0.0f; }
        }
#pragma unroll
        for (int nt = 0; nt < 8; nt++) {
            int nl = wn * 64 + nt * 8 + lr * 2;
            int ng = ncol0 + nl;
            float b0 = sBias[nl], b1 = sBias[nl + 1];
            float v00 = fmaxf(c[mt][nt][0] + b0, 0.0f);
            float v01 = fmaxf(c[mt][nt][1] + b1, 0.0f);
            float v10 = fmaxf(c[mt][nt][2] + b0, 0.0f);
            float v11 = fmaxf(c[mt][nt][3] + b1, 0.0f);
            if (MODE == 0) {
                uint32_t lo0, lo1;
                uint32_t hi0 = pack_split_hi(v00, v01, lo0);
                uint32_t hi1 = pack_split_hi(v10, v11, lo1);
                *(uint32_t*)(outH + r0 * NHID + ng) = hi0;
                *(uint32_t*)(outL + r0 * NHID + ng) = lo0;
                *(uint32_t*)(outH + r1 * NHID + ng) = hi1;
                *(uint32_t*)(outL + r1 * NHID + ng) = lo1;
            } else {
#pragma unroll
                for (int o = 0; o < NOUT; o++) {
                    float w0 = sOutW[o * BN + nl];
                    float w1 = sOutW[o * BN + nl + 1];
                    p0[o] = fmaf(v00, w0, fmaf(v01, w1, p0[o]));
                    p1[o] = fmaf(v10, w0, fmaf(v11, w1, p1[o]));
                }
            }
        }
        if (MODE == 1) {
#pragma unroll
            for (int off = 1; off <= 2; off <<= 1)
#pragma unroll
                for (int o = 0; o < NOUT; o++) {
                    p0[o] += __shfl_xor_sync(0xFFFFFFFF, p0[o], off);
                    p1[o] += __shfl_xor_sync(0xFFFFFFFF, p1[o], off);
                }
            if (lr == 0) {
#pragma unroll
                for (int o = 0; o < NOUT; o++) {
                    atomicAdd(outO + r0 * NOUT + o, p0[o]);
                    atomicAdd(outO + r1 * NOUT + o, p1[o]);
                }
            }
        }
    }
}

// ---------------------------------------------------------------------------
// Launch
// ---------------------------------------------------------------------------
extern "C" void kernel_launch(void* const* d_in, const int* in_sizes, int n_in,
                              void* d_out, int out_size) {
    const float* x      = (const float*)d_in[0];
    const float* conv_w = (const float*)d_in[1];
    const float* fc1_w  = (const float*)d_in[2];
    const float* fc1_b  = (const float*)d_in[3];
    const float* fc2_w  = (const float*)d_in[4];
    const float* fc2_b  = (const float*)d_in[5];
    const float* out_w  = (const float*)d_in[6];
    const float* out_b  = (const float*)d_in[7];
    float* out = (float*)d_out;

    __nv_bfloat16 *h0h, *h0l, *w1h, *w1l, *w2h, *w2l, *h1h, *h1l;
    cudaGetSymbolAddress((void**)&h0h, g_h0h);
    cudaGetSymbolAddress((void**)&h0l, g_h0l);
    cudaGetSymbolAddress((void**)&w1h, g_w1h);
    cudaGetSymbolAddress((void**)&w1l, g_w1l);
    cudaGetSymbolAddress((void**)&w2h, g_w2h);
    cudaGetSymbolAddress((void**)&w2l, g_w2l);
    cudaGetSymbolAddress((void**)&h1h, g_h1h);
    cudaGetSymbolAddress((void**)&h1l, g_h1l);

    {
        int total = NHID * K1PAD + NHID * K2;
        wprep_kernel<<<(total + CTHR - 1) / CTHR, CTHR>>>(fc1_w, fc2_w);
    }
    {
        size_t total = (size_t)BROWS * (K1PAD / 2);
        conv_split_kernel<<<(int)((total + CTHR - 1) / CTHR), CTHR>>>(x, conv_w);
    }
    out_init_kernel<<<(BROWS * NOUT + CTHR - 1) / CTHR, CTHR>>>(out_b, out);
    {
        cudaFuncSetAttribute(gemm_kernel<0>,
                             cudaFuncAttributeMaxDynamicSharedMemorySize,
                             DSMEM_BYTES);
        dim3 grid(NHID / BN, BROWS / BM);
        gemm_kernel<0><<<grid, GTHR, DSMEM_BYTES>>>(
            h0h, h0l, w1h, w1l, fc1_b, K1PAD, h1h, h1l, nullptr, nullptr);
    }
    {
        cudaFuncSetAttribute(gemm_kernel<1>,
                             cudaFuncAttributeMaxDynamicSharedMemorySize,
                             DSMEM_BYTES);
        dim3 grid(NHID / BN, BROWS / BM);
        gemm_kernel<1><<<grid, GTHR, DSMEM_BYTES>>>(
            h1h, h1l, w2h, w2l, fc2_b, K2, nullptr, nullptr, out_w, out);
    }
}

// round 13
// speedup vs baseline: 1.5441x; 1.5441x over previous
#include <cuda_runtime.h>
#include <cuda_bf16.h>
#include <cstdint>

// ---------------------------------------------------------------------------
// DigitConvolutionalModel via warp-level mma.sync (bf16 split hi/lo, fp32
// accum). R13 = R11 + statically-unrolled distance-4 MMA interleave
// (no pointer indirection; per-accumulator order unchanged -> bit-identical).
// ---------------------------------------------------------------------------

#define BROWS  32768
#define K1RAW  676
#define K1PAD  704          // 22 * 32
#define K2     512
#define NHID   512
#define NOUT   10
#define CTHR   256

#define BM 128
#define BN 128
#define BK 32
#define GTHR 256            // 8 warps: 4 (m) x 2 (n); warp tile 32 x 64

// dynamic smem layout (u32 units)
#define ST_A_H   0
#define ST_A_L   2560
#define ST_B_H   5120
#define ST_B_L   7680
#define ST_SIZE  10240              // one stage = 40960 B
#define ST_BIAS  (2 * ST_SIZE)      // float[128]
#define ST_OUTW  (ST_BIAS + 128)    // float[10][128]
#define DSMEM_BYTES ((2 * ST_SIZE + 128 + 1280) * 4 + 256)

// ---- scratch ---------------------------------------------------------------
__device__ __align__(16) __nv_bfloat16 g_h0h[(size_t)BROWS * K1PAD];
__device__ __align__(16) __nv_bfloat16 g_h0l[(size_t)BROWS * K1PAD];
__device__ __align__(16) __nv_bfloat16 g_w1h[(size_t)NHID * K1PAD];
__device__ __align__(16) __nv_bfloat16 g_w1l[(size_t)NHID * K1PAD];
__device__ __align__(16) __nv_bfloat16 g_w2h[(size_t)NHID * K2];
__device__ __align__(16) __nv_bfloat16 g_w2l[(size_t)NHID * K2];
__device__ __align__(16) __nv_bfloat16 g_h1h[(size_t)BROWS * K2];
__device__ __align__(16) __nv_bfloat16 g_h1l[(size_t)BROWS * K2];

// ---- helpers ---------------------------------------------------------------
__device__ __forceinline__ void split_bf16(float x, __nv_bfloat16& h,
                                           __nv_bfloat16& l) {
    h = __float2bfloat16(x);
    l = __float2bfloat16(x - __bfloat162float(h));
}
__device__ __forceinline__ uint32_t pack_split_hi(float a, float b,
                                                  uint32_t& lo_pack) {
    __nv_bfloat16 ha, la, hb, lb;
    split_bf16(a, ha, la);
    split_bf16(b, hb, lb);
    lo_pack = (uint32_t)__bfloat16_as_ushort(la) |
              ((uint32_t)__bfloat16_as_ushort(lb) << 16);
    return (uint32_t)__bfloat16_as_ushort(ha) |
           ((uint32_t)__bfloat16_as_ushort(hb) << 16);
}

__device__ __forceinline__ void mma16816(float* c, const uint32_t* a,
                                         const uint32_t* b) {
    asm volatile(
        "mma.sync.aligned.m16n8k16.row.col.f32.bf16.bf16.f32 "
        "{%0,%1,%2,%3}, {%4,%5,%6,%7}, {%8,%9}, {%0,%1,%2,%3};"
        : "+f"(c[0]), "+f"(c[1]), "+f"(c[2]), "+f"(c[3])
        : "r"(a[0]), "r"(a[1]), "r"(a[2]), "r"(a[3]), "r"(b[0]), "r"(b[1]));
}
#define LDSM4(r, addr) \
    asm volatile("ldmatrix.sync.aligned.m8n8.x4.shared.b16 {%0,%1,%2,%3}, [%4];" \
        : "=r"((r)[0]), "=r"((r)[1]), "=r"((r)[2]), "=r"((r)[3]) : "r"(addr))
__device__ __forceinline__ void cp16(uint32_t saddr, const void* gaddr) {
    asm volatile("cp.async.cg.shared.global [%0], [%1], 16;"
                 :: "r"(saddr), "l"(gaddr));
}
#define CP_COMMIT() asm volatile("cp.async.commit_group;" ::: "memory")
#define CP_WAIT(n)  asm volatile("cp.async.wait_group %0;" :: "n"(n) : "memory")

// ---------------------------------------------------------------------------
// conv + split, packed u32 writes (2 outputs / thread)
// ---------------------------------------------------------------------------
__global__ void conv_split_kernel(const float* __restrict__ x,
                                  const float* __restrict__ w) {
    __shared__ float sw[9];
    int tid = threadIdx.x;
    if (tid < 9) sw[tid] = w[tid];
    __syncthreads();

    size_t idx = (size_t)blockIdx.x * blockDim.x + tid;
    if (idx >= (size_t)BROWS * (K1PAD / 2)) return;
    int b = (int)(idx / (K1PAD / 2));
    int pp = (int)(idx - (size_t)b * (K1PAD / 2));
    int p0 = pp * 2;

    float s[2] = {0.0f, 0.0f};
#pragma unroll
    for (int u = 0; u < 2; u++) {
        int p = p0 + u;
        if (p < K1RAW) {
            int i = p / 26, j = p - i * 26;
            const float* xb = x + (size_t)b * 784 + i * 28 + j;
            float acc = 0.0f;
#pragma unroll
            for (int di = 0; di < 3; di++)
#pragma unroll
                for (int dj = 0; dj < 3; dj++)
                    acc = fmaf(xb[di * 28 + dj], sw[di * 3 + dj], acc);
            s[u] = acc;
        }
    }
    uint32_t lo;
    uint32_t hi = pack_split_hi(s[0], s[1], lo);
    ((uint32_t*)g_h0h)[idx] = hi;
    ((uint32_t*)g_h0l)[idx] = lo;
}

// ---------------------------------------------------------------------------
// weight split prep
// ---------------------------------------------------------------------------
__global__ void wprep_kernel(const float* __restrict__ w1,
                             const float* __restrict__ w2) {
    int idx = blockIdx.x * blockDim.x + threadIdx.x;
    int n1 = NHID * K1PAD;
    if (idx < n1) {
        int n = idx / K1PAD, k = idx - n * K1PAD;
        float v = (k < K1RAW) ? w1[n * K1RAW + k] : 0.0f;
        __nv_bfloat16 h, l;
        split_bf16(v, h, l);
        g_w1h[idx] = h;
        g_w1l[idx] = l;
    } else {
        int j = idx - n1;
        if (j < NHID * K2) {
            float v = w2[j];
            __nv_bfloat16 h, l;
            split_bf16(v, h, l);
            g_w2h[j] = h;
            g_w2l[j] = l;
        }
    }
}

// ---------------------------------------------------------------------------
// out init: out[b][o] = out_b[o]
// ---------------------------------------------------------------------------
__global__ void out_init_kernel(const float* __restrict__ out_b,
                                float* __restrict__ out) {
    int idx = blockIdx.x * blockDim.x + threadIdx.x;
    if (idx < BROWS * NOUT) out[idx] = out_b[idx % NOUT];
}

// ---------------------------------------------------------------------------
// Tiled GEMM, split-bf16 3-pass, distance-4 static MMA interleave.
// MODE 0: out = relu(C + bias) split -> (outH, outL) bf16
// MODE 1: v = relu(C + bias); atomicAdd partial v @ out_w^T into outO
// ---------------------------------------------------------------------------
template <int MODE>
__global__ void __launch_bounds__(GTHR, 2)
gemm_kernel(const __nv_bfloat16* __restrict__ Ah,
            const __nv_bfloat16* __restrict__ Al,
            const __nv_bfloat16* __restrict__ Wh,
            const __nv_bfloat16* __restrict__ Wl,
            const float* __restrict__ bias, int K,
            __nv_bfloat16* __restrict__ outH,
            __nv_bfloat16* __restrict__ outL,
            const float* __restrict__ outW,
            float* __restrict__ outO) {
    extern __shared__ uint32_t dsm[];
    float* sBias = (float*)(dsm + ST_BIAS);
    float* sOutW = (float*)(dsm + ST_OUTW);
    const uint32_t sbase = (uint32_t)__cvta_generic_to_shared(dsm);

    const int tid = threadIdx.x;
    const int lane = tid & 31;
    const int warp = tid >> 5;
    const int wm = warp & 3;
    const int wn = warp >> 2;
    const size_t rowA0 = (size_t)blockIdx.y * BM;
    const int ncol0 = blockIdx.x * BN;

    if (tid < BN) sBias[tid] = bias[ncol0 + tid];
    if (MODE == 1) {
        for (int i = tid; i < NOUT * BN; i += GTHR) {
            int o = i >> 7, j = i & 127;
            sOutW[o * BN + j] = outW[o * NHID + ncol0 + j];
        }
    }

    float c[2][8][4];
#pragma unroll
    for (int mt = 0; mt < 2; mt++)
#pragma unroll
        for (int nt = 0; nt < 8; nt++)
#pragma unroll
            for (int i = 0; i < 4; i++) c[mt][nt][i] = 0.0f;

    const int kcn = K / BK;

    auto stage = [&](int kc, int s) {
        uint32_t sb = sbase + (uint32_t)(s * ST_SIZE * 4);
#pragma unroll
        for (int it = 0; it < 2; it++) {
            int i = tid + it * GTHR;
            int row = i >> 2, quad = i & 3;
            uint32_t soff = (uint32_t)(row * 80 + quad * 16);
            size_t ga = (rowA0 + row) * (size_t)K + kc * BK + quad * 8;
            size_t gb = (size_t)(ncol0 + row) * K + kc * BK + quad * 8;
            cp16(sb + ST_A_H * 4 + soff, Ah + ga);
            cp16(sb + ST_A_L * 4 + soff, Al + ga);
            cp16(sb + ST_B_H * 4 + soff, Wh + gb);
            cp16(sb + ST_B_L * 4 + soff, Wl + gb);
        }
    };

    stage(0, 0);
    CP_COMMIT();

    const int g = lane >> 3, lr8 = lane & 7;
    const int arsel = (g & 1) ? 8 : 0;
    const int absel = (g & 2) ? 16 : 0;
    const int brsel = (g & 2) ? 8 : 0;
    const int bbsel = (g & 1) ? 16 : 0;

    for (int kc = 0; kc < kcn; kc++) {
        if (kc + 1 < kcn) {
            stage(kc + 1, (kc + 1) & 1);
            CP_COMMIT();
            CP_WAIT(1);
        } else {
            CP_WAIT(0);
        }
        __syncthreads();

        const uint32_t sb = sbase + (uint32_t)((kc & 1) * ST_SIZE * 4);
        const uint32_t aAh = sb + ST_A_H * 4;
        const uint32_t aAl = sb + ST_A_L * 4;
        const uint32_t aBh = sb + ST_B_H * 4;
        const uint32_t aBl = sb + ST_B_L * 4;

#pragma unroll
        for (int ks = 0; ks < 2; ks++) {
            uint32_t ah[2][4], al[2][4];
#pragma unroll
            for (int mt = 0; mt < 2; mt++) {
                int r = wm * 32 + mt * 16 + lr8 + arsel;
                uint32_t off = (uint32_t)(r * 80 + ks * 32 + absel);
                LDSM4(ah[mt], aAh + off);
                LDSM4(al[mt], aAl + off);
            }
            uint32_t bhq[2][4], blq[2][4];
            {
                int nr = wn * 64 + lr8 + brsel;
                uint32_t off = (uint32_t)(nr * 80 + ks * 32 + bbsel);
                LDSM4(bhq[0], aBh + off);
                LDSM4(blq[0], aBl + off);
            }
#pragma unroll
            for (int np = 0; np < 4; np++) {
                const int cur = np & 1;
                if (np < 3) {
                    int nr = wn * 64 + (np + 1) * 16 + lr8 + brsel;
                    uint32_t off = (uint32_t)(nr * 80 + ks * 32 + bbsel);
                    LDSM4(bhq[cur ^ 1], aBh + off);
                    LDSM4(blq[cur ^ 1], aBl + off);
                }
                // Distance-4 static interleave. Per-accumulator order is
                // hh -> hl -> lh (identical to R11) so results are bit-equal.
                const int nt0 = np * 2, nt1 = np * 2 + 1;
                // pass hh
                mma16816(c[0][nt0], ah[0], bhq[cur] + 0);
                mma16816(c[1][nt0], ah[1], bhq[cur] + 0);
                mma16816(c[0][nt1], ah[0], bhq[cur] + 2);
                mma16816(c[1][nt1], ah[1], bhq[cur] + 2);
                // pass hl
                mma16816(c[0][nt0], ah[0], blq[cur] + 0);
                mma16816(c[1][nt0], ah[1], blq[cur] + 0);
                mma16816(c[0][nt1], ah[0], blq[cur] + 2);
                mma16816(c[1][nt1], ah[1], blq[cur] + 2);
                // pass lh
                mma16816(c[0][nt0], al[0], bhq[cur] + 0);
                mma16816(c[1][nt0], al[1], bhq[cur] + 0);
                mma16816(c[0][nt1], al[0], bhq[cur] + 2);
                mma16816(c[1][nt1], al[1], bhq[cur] + 2);
            }
        }
        __syncthreads();
    }

    // epilogue
    const int lq = lane >> 2;
    const int lr = lane & 3;
#pragma unroll
    for (int mt = 0; mt < 2; mt++) {
        size_t r0 = rowA0 + wm * 32 + mt * 16 + lq;
        size_t r1 = r0 + 8;
        float p0[NOUT], p1[NOUT];
        if (MODE == 1) {
#pragma unroll
            for (int o = 0; o < NOUT; o++) { p0[o] = 0.0f; p1[o] = 0.0f; }
        }
#pragma unroll
        for (int nt = 0; nt < 8; nt++) {
            int nl = wn * 64 + nt * 8 + lr * 2;
            int ng = ncol0 + nl;
            float b0 = sBias[nl], b1 = sBias[nl + 1];
            float v00 = fmaxf(c[mt][nt][0] + b0, 0.0f);
            float v01 = fmaxf(c[mt][nt][1] + b1, 0.0f);
            float v10 = fmaxf(c[mt][nt][2] + b0, 0.0f);
            float v11 = fmaxf(c[mt][nt][3] + b1, 0.0f);
            if (MODE == 0) {
                uint32_t lo0, lo1;
                uint32_t hi0 = pack_split_hi(v00, v01, lo0);
                uint32_t hi1 = pack_split_hi(v10, v11, lo1);
                *(uint32_t*)(outH + r0 * NHID + ng) = hi0;
                *(uint32_t*)(outL + r0 * NHID + ng) = lo0;
                *(uint32_t*)(outH + r1 * NHID + ng) = hi1;
                *(uint32_t*)(outL + r1 * NHID + ng) = lo1;
            } else {
#pragma unroll
                for (int o = 0; o < NOUT; o++) {
                    float w0 = sOutW[o * BN + nl];
                    float w1 = sOutW[o * BN + nl + 1];
                    p0[o] = fmaf(v00, w0, fmaf(v01, w1, p0[o]));
                    p1[o] = fmaf(v10, w0, fmaf(v11, w1, p1[o]));
                }
            }
        }
        if (MODE == 1) {
#pragma unroll
            for (int off = 1; off <= 2; off <<= 1)
#pragma unroll
                for (int o = 0; o < NOUT; o++) {
                    p0[o] += __shfl_xor_sync(0xFFFFFFFF, p0[o], off);
                    p1[o] += __shfl_xor_sync(0xFFFFFFFF, p1[o], off);
                }
            if (lr == 0) {
#pragma unroll
                for (int o = 0; o < NOUT; o++) {
                    atomicAdd(outO + r0 * NOUT + o, p0[o]);
                    atomicAdd(outO + r1 * NOUT + o, p1[o]);
                }
            }
        }
    }
}

// ---------------------------------------------------------------------------
// Launch
// ---------------------------------------------------------------------------
extern "C" void kernel_launch(void* const* d_in, const int* in_sizes, int n_in,
                              void* d_out, int out_size) {
    const float* x      = (const float*)d_in[0];
    const float* conv_w = (const float*)d_in[1];
    const float* fc1_w  = (const float*)d_in[2];
    const float* fc1_b  = (const float*)d_in[3];
    const float* fc2_w  = (const float*)d_in[4];
    const float* fc2_b  = (const float*)d_in[5];
    const float* out_w  = (const float*)d_in[6];
    const float* out_b  = (const float*)d_in[7];
    float* out = (float*)d_out;

    __nv_bfloat16 *h0h, *h0l, *w1h, *w1l, *w2h, *w2l, *h1h, *h1l;
    cudaGetSymbolAddress((void**)&h0h, g_h0h);
    cudaGetSymbolAddress((void**)&h0l, g_h0l);
    cudaGetSymbolAddress((void**)&w1h, g_w1h);
    cudaGetSymbolAddress((void**)&w1l, g_w1l);
    cudaGetSymbolAddress((void**)&w2h, g_w2h);
    cudaGetSymbolAddress((void**)&w2l, g_w2l);
    cudaGetSymbolAddress((void**)&h1h, g_h1h);
    cudaGetSymbolAddress((void**)&h1l, g_h1l);

    {
        int total = NHID * K1PAD + NHID * K2;
        wprep_kernel<<<(total + CTHR - 1) / CTHR, CTHR>>>(fc1_w, fc2_w);
    }
    {
        size_t total = (size_t)BROWS * (K1PAD / 2);
        conv_split_kernel<<<(int)((total + CTHR - 1) / CTHR), CTHR>>>(x, conv_w);
    }
    out_init_kernel<<<(BROWS * NOUT + CTHR - 1) / CTHR, CTHR>>>(out_b, out);
    {
        cudaFuncSetAttribute(gemm_kernel<0>,
                             cudaFuncAttributeMaxDynamicSharedMemorySize,
                             DSMEM_BYTES);
        dim3 grid(NHID / BN, BROWS / BM);
        gemm_kernel<0><<<grid, GTHR, DSMEM_BYTES>>>(
            h0h, h0l, w1h, w1l, fc1_b, K1PAD, h1h, h1l, nullptr, nullptr);
    }
    {
        cudaFuncSetAttribute(gemm_kernel<1>,
                             cudaFuncAttributeMaxDynamicSharedMemorySize,
                             DSMEM_BYTES);
        dim3 grid(NHID / BN, BROWS / BM);
        gemm_kernel<1><<<grid, GTHR, DSMEM_BYTES>>>(
            h1h, h1l, w2h, w2l, fc2_b, K2, nullptr, nullptr, out_w, out);
    }
}

// round 14
// speedup vs baseline: 1.6151x; 1.0460x over previous
#include <cuda_runtime.h>
#include <cuda_bf16.h>
#include <cstdint>

// ---------------------------------------------------------------------------
// DigitConvolutionalModel via warp-level mma.sync (bf16 split hi/lo, fp32
// accum). R14: 64x64 warp tiles (4 warps/CTA) cut smem-crossbar traffic 33%
// (the measured bottleneck); conv rewritten with coalesced smem staging.
// ---------------------------------------------------------------------------

#define BROWS  32768
#define K1RAW  676
#define K1PAD  704          // 22 * 32
#define K2     512
#define NHID   512
#define NOUT   10
#define CTHR   256

#define BM 128
#define BN 128
#define BK 32
#define GTHR 128            // 4 warps: 2 (m) x 2 (n); warp tile 64 x 64

// dynamic smem layout (u32 units)
#define ST_A_H   0
#define ST_A_L   2560
#define ST_B_H   5120
#define ST_B_L   7680
#define ST_SIZE  10240              // one stage = 40960 B
#define ST_BIAS  (2 * ST_SIZE)      // float[128]
#define ST_OUTW  (ST_BIAS + 128)    // float[10][128]
#define DSMEM_BYTES ((2 * ST_SIZE + 128 + 1280) * 4 + 256)

// ---- scratch ---------------------------------------------------------------
__device__ __align__(16) __nv_bfloat16 g_h0h[(size_t)BROWS * K1PAD];
__device__ __align__(16) __nv_bfloat16 g_h0l[(size_t)BROWS * K1PAD];
__device__ __align__(16) __nv_bfloat16 g_w1h[(size_t)NHID * K1PAD];
__device__ __align__(16) __nv_bfloat16 g_w1l[(size_t)NHID * K1PAD];
__device__ __align__(16) __nv_bfloat16 g_w2h[(size_t)NHID * K2];
__device__ __align__(16) __nv_bfloat16 g_w2l[(size_t)NHID * K2];
__device__ __align__(16) __nv_bfloat16 g_h1h[(size_t)BROWS * K2];
__device__ __align__(16) __nv_bfloat16 g_h1l[(size_t)BROWS * K2];

// ---- helpers ---------------------------------------------------------------
__device__ __forceinline__ void split_bf16(float x, __nv_bfloat16& h,
                                           __nv_bfloat16& l) {
    h = __float2bfloat16(x);
    l = __float2bfloat16(x - __bfloat162float(h));
}
__device__ __forceinline__ uint32_t pack_split_hi(float a, float b,
                                                  uint32_t& lo_pack) {
    __nv_bfloat16 ha, la, hb, lb;
    split_bf16(a, ha, la);
    split_bf16(b, hb, lb);
    lo_pack = (uint32_t)__bfloat16_as_ushort(la) |
              ((uint32_t)__bfloat16_as_ushort(lb) << 16);
    return (uint32_t)__bfloat16_as_ushort(ha) |
           ((uint32_t)__bfloat16_as_ushort(hb) << 16);
}

__device__ __forceinline__ void mma16816(float* c, const uint32_t* a,
                                         const uint32_t* b) {
    asm volatile(
        "mma.sync.aligned.m16n8k16.row.col.f32.bf16.bf16.f32 "
        "{%0,%1,%2,%3}, {%4,%5,%6,%7}, {%8,%9}, {%0,%1,%2,%3};"
        : "+f"(c[0]), "+f"(c[1]), "+f"(c[2]), "+f"(c[3])
        : "r"(a[0]), "r"(a[1]), "r"(a[2]), "r"(a[3]), "r"(b[0]), "r"(b[1]));
}
#define LDSM4(r, addr) \
    asm volatile("ldmatrix.sync.aligned.m8n8.x4.shared.b16 {%0,%1,%2,%3}, [%4];" \
        : "=r"((r)[0]), "=r"((r)[1]), "=r"((r)[2]), "=r"((r)[3]) : "r"(addr))
__device__ __forceinline__ void cp16(uint32_t saddr, const void* gaddr) {
    asm volatile("cp.async.cg.shared.global [%0], [%1], 16;"
                 :: "r"(saddr), "l"(gaddr));
}
#define CP_COMMIT() asm volatile("cp.async.commit_group;" ::: "memory")
#define CP_WAIT(n)  asm volatile("cp.async.wait_group %0;" :: "n"(n) : "memory")

// ---------------------------------------------------------------------------
// conv + split: 4 images per CTA, coalesced float4 smem staging.
// ---------------------------------------------------------------------------
__global__ void __launch_bounds__(CTHR)
conv_split_kernel(const float* __restrict__ x,
                  const float* __restrict__ w) {
    __shared__ float sx[4 * 784];
    __shared__ float sw[9];
    int tid = threadIdx.x;
    if (tid < 9) sw[tid] = w[tid];

    // stage 4 images (3136 floats = 784 float4, contiguous) coalesced
    const float4* src = (const float4*)(x + (size_t)blockIdx.x * 4 * 784);
    float4* dst = (float4*)sx;
#pragma unroll
    for (int it = 0; it < 4; it++) {
        int idx = tid + it * CTHR;
        if (idx < 784) dst[idx] = src[idx];
    }
    __syncthreads();

    const size_t pairbase = (size_t)blockIdx.x * 4 * (K1PAD / 2);
#pragma unroll
    for (int it = 0; it < 6; it++) {
        int task = tid + it * CTHR;           // 0..1407
        if (task >= 4 * (K1PAD / 2)) break;
        int img = task / (K1PAD / 2);
        int pp = task - img * (K1PAD / 2);
        int p0 = pp * 2;
        const float* sxi = sx + img * 784;

        float s[2] = {0.0f, 0.0f};
#pragma unroll
        for (int u = 0; u < 2; u++) {
            int p = p0 + u;
            if (p < K1RAW) {
                int i = p / 26, j = p - i * 26;
                const float* xb = sxi + i * 28 + j;
                float acc = 0.0f;
#pragma unroll
                for (int di = 0; di < 3; di++)
#pragma unroll
                    for (int dj = 0; dj < 3; dj++)
                        acc = fmaf(xb[di * 28 + dj], sw[di * 3 + dj], acc);
                s[u] = acc;
            }
        }
        uint32_t lo;
        uint32_t hi = pack_split_hi(s[0], s[1], lo);
        ((uint32_t*)g_h0h)[pairbase + task] = hi;
        ((uint32_t*)g_h0l)[pairbase + task] = lo;
    }
}

// ---------------------------------------------------------------------------
// weight split prep
// ---------------------------------------------------------------------------
__global__ void wprep_kernel(const float* __restrict__ w1,
                             const float* __restrict__ w2) {
    int idx = blockIdx.x * blockDim.x + threadIdx.x;
    int n1 = NHID * K1PAD;
    if (idx < n1) {
        int n = idx / K1PAD, k = idx - n * K1PAD;
        float v = (k < K1RAW) ? w1[n * K1RAW + k] : 0.0f;
        __nv_bfloat16 h, l;
        split_bf16(v, h, l);
        g_w1h[idx] = h;
        g_w1l[idx] = l;
    } else {
        int j = idx - n1;
        if (j < NHID * K2) {
            float v = w2[j];
            __nv_bfloat16 h, l;
            split_bf16(v, h, l);
            g_w2h[j] = h;
            g_w2l[j] = l;
        }
    }
}

// ---------------------------------------------------------------------------
// out init: out[b][o] = out_b[o]
// ---------------------------------------------------------------------------
__global__ void out_init_kernel(const float* __restrict__ out_b,
                                float* __restrict__ out) {
    int idx = blockIdx.x * blockDim.x + threadIdx.x;
    if (idx < BROWS * NOUT) out[idx] = out_b[idx % NOUT];
}

// ---------------------------------------------------------------------------
// Tiled GEMM, split-bf16 3-pass, 4 warps of 64x64 (min smem duplication).
// MODE 0: out = relu(C + bias) split -> (outH, outL) bf16
// MODE 1: v = relu(C + bias); atomicAdd partial v @ out_w^T into outO
// ---------------------------------------------------------------------------
template <int MODE>
__global__ void __launch_bounds__(GTHR, 2)
gemm_kernel(const __nv_bfloat16* __restrict__ Ah,
            const __nv_bfloat16* __restrict__ Al,
            const __nv_bfloat16* __restrict__ Wh,
            const __nv_bfloat16* __restrict__ Wl,
            const float* __restrict__ bias, int K,
            __nv_bfloat16* __restrict__ outH,
            __nv_bfloat16* __restrict__ outL,
            const float* __restrict__ outW,
            float* __restrict__ outO) {
    extern __shared__ uint32_t dsm[];
    float* sBias = (float*)(dsm + ST_BIAS);
    float* sOutW = (float*)(dsm + ST_OUTW);
    const uint32_t sbase = (uint32_t)__cvta_generic_to_shared(dsm);

    const int tid = threadIdx.x;
    const int lane = tid & 31;
    const int warp = tid >> 5;           // 0..3
    const int wm = warp & 1;             // 64-row half
    const int wn = warp >> 1;            // 64-col half
    const size_t rowA0 = (size_t)blockIdx.y * BM;
    const int ncol0 = blockIdx.x * BN;

    if (tid < BN) sBias[tid] = bias[ncol0 + tid];
    if (MODE == 1) {
#pragma unroll
        for (int it = 0; it < 10; it++) {
            int i = tid + it * GTHR;     // 1280 total
            int o = i >> 7, j = i & 127;
            sOutW[o * BN + j] = outW[o * NHID + ncol0 + j];
        }
    }

    float c[4][8][4];
#pragma unroll
    for (int mt = 0; mt < 4; mt++)
#pragma unroll
        for (int nt = 0; nt < 8; nt++)
#pragma unroll
            for (int i = 0; i < 4; i++) c[mt][nt][i] = 0.0f;

    const int kcn = K / BK;

    auto stage = [&](int kc, int s) {
        uint32_t sb = sbase + (uint32_t)(s * ST_SIZE * 4);
#pragma unroll
        for (int it = 0; it < 4; it++) {
            int i = tid + it * GTHR;     // 0..511
            int row = i >> 2, quad = i & 3;
            uint32_t soff = (uint32_t)(row * 80 + quad * 16);
            size_t ga = (rowA0 + row) * (size_t)K + kc * BK + quad * 8;
            size_t gb = (size_t)(ncol0 + row) * K + kc * BK + quad * 8;
            cp16(sb + ST_A_H * 4 + soff, Ah + ga);
            cp16(sb + ST_A_L * 4 + soff, Al + ga);
            cp16(sb + ST_B_H * 4 + soff, Wh + gb);
            cp16(sb + ST_B_L * 4 + soff, Wl + gb);
        }
    };

    stage(0, 0);
    CP_COMMIT();

    const int g = lane >> 3, lr8 = lane & 7;
    const int arsel = (g & 1) ? 8 : 0;
    const int absel = (g & 2) ? 16 : 0;
    const int brsel = (g & 2) ? 8 : 0;
    const int bbsel = (g & 1) ? 16 : 0;

    for (int kc = 0; kc < kcn; kc++) {
        if (kc + 1 < kcn) {
            stage(kc + 1, (kc + 1) & 1);
            CP_COMMIT();
            CP_WAIT(1);
        } else {
            CP_WAIT(0);
        }
        __syncthreads();

        const uint32_t sb = sbase + (uint32_t)((kc & 1) * ST_SIZE * 4);
        const uint32_t aAh = sb + ST_A_H * 4;
        const uint32_t aAl = sb + ST_A_L * 4;
        const uint32_t aBh = sb + ST_B_H * 4;
        const uint32_t aBl = sb + ST_B_L * 4;

#pragma unroll
        for (int ks = 0; ks < 2; ks++) {
            uint32_t ah[4][4], al[4][4];
#pragma unroll
            for (int mt = 0; mt < 4; mt++) {
                int r = wm * 64 + mt * 16 + lr8 + arsel;
                uint32_t off = (uint32_t)(r * 80 + ks * 32 + absel);
                LDSM4(ah[mt], aAh + off);
                LDSM4(al[mt], aAl + off);
            }
            uint32_t bh[4][4], bl[4][4];
#pragma unroll
            for (int nq = 0; nq < 4; nq++) {
                int nr = wn * 64 + nq * 16 + lr8 + brsel;
                uint32_t off = (uint32_t)(nr * 80 + ks * 32 + bbsel);
                LDSM4(bh[nq], aBh + off);
                LDSM4(bl[nq], aBl + off);
            }
#pragma unroll
            for (int nq = 0; nq < 4; nq++) {
#pragma unroll
                for (int hf = 0; hf < 2; hf++) {
                    const int nt = nq * 2 + hf;
                    // per-acc order hh -> hl -> lh (bit-identical to R11)
#pragma unroll
                    for (int mt = 0; mt < 4; mt++)
                        mma16816(c[mt][nt], ah[mt], bh[nq] + 2 * hf);
#pragma unroll
                    for (int mt = 0; mt < 4; mt++)
                        mma16816(c[mt][nt], ah[mt], bl[nq] + 2 * hf);
#pragma unroll
                    for (int mt = 0; mt < 4; mt++)
                        mma16816(c[mt][nt], al[mt], bh[nq] + 2 * hf);
                }
            }
        }
        __syncthreads();
    }

    // epilogue
    const int lq = lane >> 2;
    const int lr = lane & 3;
#pragma unroll
    for (int mt = 0; mt < 4; mt++) {
        size_t r0 = rowA0 + wm * 64 + mt * 16 + lq;
        size_t r1 = r0 + 8;
        float p0[NOUT], p1[NOUT];
        if (MODE == 1) {
#pragma unroll
            for (int o = 0; o < NOUT; o++) { p0[o] = 0.0f; p1[o] = 0.0f; }
        }
#pragma unroll
        for (int nt = 0; nt < 8; nt++) {
            int nl = wn * 64 + nt * 8 + lr * 2;
            int ng = ncol0 + nl;
            float b0 = sBias[nl], b1 = sBias[nl + 1];
            float v00 = fmaxf(c[mt][nt][0] + b0, 0.0f);
            float v01 = fmaxf(c[mt][nt][1] + b1, 0.0f);
            float v10 = fmaxf(c[mt][nt][2] + b0, 0.0f);
            float v11 = fmaxf(c[mt][nt][3] + b1, 0.0f);
            if (MODE == 0) {
                uint32_t lo0, lo1;
                uint32_t hi0 = pack_split_hi(v00, v01, lo0);
                uint32_t hi1 = pack_split_hi(v10, v11, lo1);
                *(uint32_t*)(outH + r0 * NHID + ng) = hi0;
                *(uint32_t*)(outL + r0 * NHID + ng) = lo0;
                *(uint32_t*)(outH + r1 * NHID + ng) = hi1;
                *(uint32_t*)(outL + r1 * NHID + ng) = lo1;
            } else {
#pragma unroll
                for (int o = 0; o < NOUT; o++) {
                    float w0 = sOutW[o * BN + nl];
                    float w1 = sOutW[o * BN + nl + 1];
                    p0[o] = fmaf(v00, w0, fmaf(v01, w1, p0[o]));
                    p1[o] = fmaf(v10, w0, fmaf(v11, w1, p1[o]));
                }
            }
        }
        if (MODE == 1) {
#pragma unroll
            for (int off = 1; off <= 2; off <<= 1)
#pragma unroll
                for (int o = 0; o < NOUT; o++) {
                    p0[o] += __shfl_xor_sync(0xFFFFFFFF, p0[o], off);
                    p1[o] += __shfl_xor_sync(0xFFFFFFFF, p1[o], off);
                }
            if (lr == 0) {
#pragma unroll
                for (int o = 0; o < NOUT; o++) {
                    atomicAdd(outO + r0 * NOUT + o, p0[o]);
                    atomicAdd(outO + r1 * NOUT + o, p1[o]);
                }
            }
        }
    }
}

// ---------------------------------------------------------------------------
// Launch
// ---------------------------------------------------------------------------
extern "C" void kernel_launch(void* const* d_in, const int* in_sizes, int n_in,
                              void* d_out, int out_size) {
    const float* x      = (const float*)d_in[0];
    const float* conv_w = (const float*)d_in[1];
    const float* fc1_w  = (const float*)d_in[2];
    const float* fc1_b  = (const float*)d_in[3];
    const float* fc2_w  = (const float*)d_in[4];
    const float* fc2_b  = (const float*)d_in[5];
    const float* out_w  = (const float*)d_in[6];
    const float* out_b  = (const float*)d_in[7];
    float* out = (float*)d_out;

    __nv_bfloat16 *h0h, *h0l, *w1h, *w1l, *w2h, *w2l, *h1h, *h1l;
    cudaGetSymbolAddress((void**)&h0h, g_h0h);
    cudaGetSymbolAddress((void**)&h0l, g_h0l);
    cudaGetSymbolAddress((void**)&w1h, g_w1h);
    cudaGetSymbolAddress((void**)&w1l, g_w1l);
    cudaGetSymbolAddress((void**)&w2h, g_w2h);
    cudaGetSymbolAddress((void**)&w2l, g_w2l);
    cudaGetSymbolAddress((void**)&h1h, g_h1h);
    cudaGetSymbolAddress((void**)&h1l, g_h1l);

    {
        int total = NHID * K1PAD + NHID * K2;
        wprep_kernel<<<(total + CTHR - 1) / CTHR, CTHR>>>(fc1_w, fc2_w);
    }
    conv_split_kernel<<<BROWS / 4, CTHR>>>(x, conv_w);
    out_init_kernel<<<(BROWS * NOUT + CTHR - 1) / CTHR, CTHR>>>(out_b, out);
    {
        cudaFuncSetAttribute(gemm_kernel<0>,
                             cudaFuncAttributeMaxDynamicSharedMemorySize,
                             DSMEM_BYTES);
        dim3 grid(NHID / BN, BROWS / BM);
        gemm_kernel<0><<<grid, GTHR, DSMEM_BYTES>>>(
            h0h, h0l, w1h, w1l, fc1_b, K1PAD, h1h, h1l, nullptr, nullptr);
    }
    {
        cudaFuncSetAttribute(gemm_kernel<1>,
                             cudaFuncAttributeMaxDynamicSharedMemorySize,
                             DSMEM_BYTES);
        dim3 grid(NHID / BN, BROWS / BM);
        gemm_kernel<1><<<grid, GTHR, DSMEM_BYTES>>>(
            h1h, h1l, w2h, w2l, fc2_b, K2, nullptr, nullptr, out_w, out);
    }
}

// round 15
// speedup vs baseline: 1.7818x; 1.1033x over previous
#include <cuda_runtime.h>
#include <cuda_bf16.h>
#include <cstdint>

// ---------------------------------------------------------------------------
// DigitConvolutionalModel via warp-level mma.sync (bf16 split hi/lo, fp32
// accum). R15: streamlined conv (16 img/CTA, exact task loop), merged prep
// kernel, smem-combined out-layer partials (halved global atomics).
// GEMM mainloop identical to R14 (best known).
// ---------------------------------------------------------------------------

#define BROWS  32768
#define K1RAW  676
#define K1PAD  704          // 22 * 32
#define K2     512
#define NHID   512
#define NOUT   10
#define CTHR   256

#define BM 128
#define BN 128
#define BK 32
#define GTHR 128            // 4 warps: 2 (m) x 2 (n); warp tile 64 x 64

// dynamic smem layout (u32 units)
#define ST_A_H   0
#define ST_A_L   2560
#define ST_B_H   5120
#define ST_B_L   7680
#define ST_SIZE  10240              // one stage = 40960 B
#define ST_BIAS  (2 * ST_SIZE)      // float[128]
#define ST_OUTW  (ST_BIAS + 128)    // float[10][128]
#define ST_PART  (ST_OUTW + 1280)   // float[128][10]
#define DSMEM_BYTES ((2 * ST_SIZE + 128 + 1280 + 1280) * 4 + 256)

// ---- scratch ---------------------------------------------------------------
__device__ __align__(16) __nv_bfloat16 g_h0h[(size_t)BROWS * K1PAD];
__device__ __align__(16) __nv_bfloat16 g_h0l[(size_t)BROWS * K1PAD];
__device__ __align__(16) __nv_bfloat16 g_w1h[(size_t)NHID * K1PAD];
__device__ __align__(16) __nv_bfloat16 g_w1l[(size_t)NHID * K1PAD];
__device__ __align__(16) __nv_bfloat16 g_w2h[(size_t)NHID * K2];
__device__ __align__(16) __nv_bfloat16 g_w2l[(size_t)NHID * K2];
__device__ __align__(16) __nv_bfloat16 g_h1h[(size_t)BROWS * K2];
__device__ __align__(16) __nv_bfloat16 g_h1l[(size_t)BROWS * K2];

// ---- helpers ---------------------------------------------------------------
__device__ __forceinline__ void split_bf16(float x, __nv_bfloat16& h,
                                           __nv_bfloat16& l) {
    h = __float2bfloat16(x);
    l = __float2bfloat16(x - __bfloat162float(h));
}
__device__ __forceinline__ uint32_t pack_split_hi(float a, float b,
                                                  uint32_t& lo_pack) {
    __nv_bfloat16 ha, la, hb, lb;
    split_bf16(a, ha, la);
    split_bf16(b, hb, lb);
    lo_pack = (uint32_t)__bfloat16_as_ushort(la) |
              ((uint32_t)__bfloat16_as_ushort(lb) << 16);
    return (uint32_t)__bfloat16_as_ushort(ha) |
           ((uint32_t)__bfloat16_as_ushort(hb) << 16);
}

__device__ __forceinline__ void mma16816(float* c, const uint32_t* a,
                                         const uint32_t* b) {
    asm volatile(
        "mma.sync.aligned.m16n8k16.row.col.f32.bf16.bf16.f32 "
        "{%0,%1,%2,%3}, {%4,%5,%6,%7}, {%8,%9}, {%0,%1,%2,%3};"
        : "+f"(c[0]), "+f"(c[1]), "+f"(c[2]), "+f"(c[3])
        : "r"(a[0]), "r"(a[1]), "r"(a[2]), "r"(a[3]), "r"(b[0]), "r"(b[1]));
}
#define LDSM4(r, addr) \
    asm volatile("ldmatrix.sync.aligned.m8n8.x4.shared.b16 {%0,%1,%2,%3}, [%4];" \
        : "=r"((r)[0]), "=r"((r)[1]), "=r"((r)[2]), "=r"((r)[3]) : "r"(addr))
__device__ __forceinline__ void cp16(uint32_t saddr, const void* gaddr) {
    asm volatile("cp.async.cg.shared.global [%0], [%1], 16;"
                 :: "r"(saddr), "l"(gaddr));
}
#define CP_COMMIT() asm volatile("cp.async.commit_group;" ::: "memory")
#define CP_WAIT(n)  asm volatile("cp.async.wait_group %0;" :: "n"(n) : "memory")

// ---------------------------------------------------------------------------
// conv + split: 16 images per CTA; exact 22-iter task loop (5632 = 256*22).
// ---------------------------------------------------------------------------
#define CONV_IMGS 16
#define PAIRS_PER_IMG (K1PAD / 2)   // 352
__global__ void __launch_bounds__(CTHR)
conv_split_kernel(const float* __restrict__ x,
                  const float* __restrict__ w) {
    __shared__ float sx[CONV_IMGS * 784];
    __shared__ float sw[9];
    int tid = threadIdx.x;
    if (tid < 9) sw[tid] = w[tid];

    const float4* src = (const float4*)(x + (size_t)blockIdx.x * CONV_IMGS * 784);
    float4* dst = (float4*)sx;
#pragma unroll
    for (int it = 0; it < 13; it++) {
        int idx = tid + it * CTHR;
        if (idx < CONV_IMGS * 196) dst[idx] = src[idx];
    }
    __syncthreads();

    const size_t pairbase = (size_t)blockIdx.x * CONV_IMGS * PAIRS_PER_IMG;
#pragma unroll
    for (int it = 0; it < 22; it++) {
        int task = tid + it * CTHR;             // 0..5631, exact
        int img = task / PAIRS_PER_IMG;
        int pp = task - img * PAIRS_PER_IMG;
        int p0 = pp * 2;
        const float* sxi = sx + img * 784;

        float s[2] = {0.0f, 0.0f};
#pragma unroll
        for (int u = 0; u < 2; u++) {
            int p = p0 + u;
            if (p < K1RAW) {
                int i = p / 26, j = p - i * 26;
                const float* xb = sxi + i * 28 + j;
                float acc = 0.0f;
#pragma unroll
                for (int di = 0; di < 3; di++)
#pragma unroll
                    for (int dj = 0; dj < 3; dj++)
                        acc = fmaf(xb[di * 28 + dj], sw[di * 3 + dj], acc);
                s[u] = acc;
            }
        }
        uint32_t lo;
        uint32_t hi = pack_split_hi(s[0], s[1], lo);
        ((uint32_t*)g_h0h)[pairbase + task] = hi;
        ((uint32_t*)g_h0l)[pairbase + task] = lo;
    }
}

// ---------------------------------------------------------------------------
// merged prep: weight split (w1, w2) + out init.  Ranges:
//   [0, 360448)            w1 split (pad 676->704)
//   [360448, 622592)       w2 split
//   [622592, 950272)       out[b][o] = out_b[o]
// ---------------------------------------------------------------------------
#define PREP_W1  (NHID * K1PAD)                 // 360448
#define PREP_W2  (PREP_W1 + NHID * K2)          // 622592
#define PREP_END (PREP_W2 + BROWS * NOUT)       // 950272
__global__ void prep_kernel(const float* __restrict__ w1,
                            const float* __restrict__ w2,
                            const float* __restrict__ out_b,
                            float* __restrict__ out) {
    int idx = blockIdx.x * blockDim.x + threadIdx.x;
    if (idx < PREP_W1) {
        int n = idx / K1PAD, k = idx - n * K1PAD;
        float v = (k < K1RAW) ? w1[n * K1RAW + k] : 0.0f;
        __nv_bfloat16 h, l;
        split_bf16(v, h, l);
        g_w1h[idx] = h;
        g_w1l[idx] = l;
    } else if (idx < PREP_W2) {
        int j = idx - PREP_W1;
        float v = w2[j];
        __nv_bfloat16 h, l;
        split_bf16(v, h, l);
        g_w2h[j] = h;
        g_w2l[j] = l;
    } else if (idx < PREP_END) {
        int j = idx - PREP_W2;
        out[j] = out_b[j % NOUT];
    }
}

// ---------------------------------------------------------------------------
// Tiled GEMM, split-bf16 3-pass, 4 warps of 64x64 (mainloop = R14).
// MODE 0: out = relu(C + bias) split -> (outH, outL) bf16
// MODE 1: v = relu(C + bias); out-layer partials combined in smem, then
//         a single atomicAdd per (row, o) per CTA.
// ---------------------------------------------------------------------------
template <int MODE>
__global__ void __launch_bounds__(GTHR, 2)
gemm_kernel(const __nv_bfloat16* __restrict__ Ah,
            const __nv_bfloat16* __restrict__ Al,
            const __nv_bfloat16* __restrict__ Wh,
            const __nv_bfloat16* __restrict__ Wl,
            const float* __restrict__ bias, int K,
            __nv_bfloat16* __restrict__ outH,
            __nv_bfloat16* __restrict__ outL,
            const float* __restrict__ outW,
            float* __restrict__ outO) {
    extern __shared__ uint32_t dsm[];
    float* sBias = (float*)(dsm + ST_BIAS);
    float* sOutW = (float*)(dsm + ST_OUTW);
    float* sPart = (float*)(dsm + ST_PART);
    const uint32_t sbase = (uint32_t)__cvta_generic_to_shared(dsm);

    const int tid = threadIdx.x;
    const int lane = tid & 31;
    const int warp = tid >> 5;           // 0..3
    const int wm = warp & 1;
    const int wn = warp >> 1;
    const size_t rowA0 = (size_t)blockIdx.y * BM;
    const int ncol0 = blockIdx.x * BN;

    if (tid < BN) sBias[tid] = bias[ncol0 + tid];
    if (MODE == 1) {
#pragma unroll
        for (int it = 0; it < 10; it++) {
            int i = tid + it * GTHR;
            int o = i >> 7, j = i & 127;
            sOutW[o * BN + j] = outW[o * NHID + ncol0 + j];
        }
    }

    float c[4][8][4];
#pragma unroll
    for (int mt = 0; mt < 4; mt++)
#pragma unroll
        for (int nt = 0; nt < 8; nt++)
#pragma unroll
            for (int i = 0; i < 4; i++) c[mt][nt][i] = 0.0f;

    const int kcn = K / BK;

    auto stage = [&](int kc, int s) {
        uint32_t sb = sbase + (uint32_t)(s * ST_SIZE * 4);
#pragma unroll
        for (int it = 0; it < 4; it++) {
            int i = tid + it * GTHR;
            int row = i >> 2, quad = i & 3;
            uint32_t soff = (uint32_t)(row * 80 + quad * 16);
            size_t ga = (rowA0 + row) * (size_t)K + kc * BK + quad * 8;
            size_t gb = (size_t)(ncol0 + row) * K + kc * BK + quad * 8;
            cp16(sb + ST_A_H * 4 + soff, Ah + ga);
            cp16(sb + ST_A_L * 4 + soff, Al + ga);
            cp16(sb + ST_B_H * 4 + soff, Wh + gb);
            cp16(sb + ST_B_L * 4 + soff, Wl + gb);
        }
    };

    stage(0, 0);
    CP_COMMIT();

    const int g = lane >> 3, lr8 = lane & 7;
    const int arsel = (g & 1) ? 8 : 0;
    const int absel = (g & 2) ? 16 : 0;
    const int brsel = (g & 2) ? 8 : 0;
    const int bbsel = (g & 1) ? 16 : 0;

    for (int kc = 0; kc < kcn; kc++) {
        if (kc + 1 < kcn) {
            stage(kc + 1, (kc + 1) & 1);
            CP_COMMIT();
            CP_WAIT(1);
        } else {
            CP_WAIT(0);
        }
        __syncthreads();

        const uint32_t sb = sbase + (uint32_t)((kc & 1) * ST_SIZE * 4);
        const uint32_t aAh = sb + ST_A_H * 4;
        const uint32_t aAl = sb + ST_A_L * 4;
        const uint32_t aBh = sb + ST_B_H * 4;
        const uint32_t aBl = sb + ST_B_L * 4;

#pragma unroll
        for (int ks = 0; ks < 2; ks++) {
            uint32_t ah[4][4], al[4][4];
#pragma unroll
            for (int mt = 0; mt < 4; mt++) {
                int r = wm * 64 + mt * 16 + lr8 + arsel;
                uint32_t off = (uint32_t)(r * 80 + ks * 32 + absel);
                LDSM4(ah[mt], aAh + off);
                LDSM4(al[mt], aAl + off);
            }
            uint32_t bh[4][4], bl[4][4];
#pragma unroll
            for (int nq = 0; nq < 4; nq++) {
                int nr = wn * 64 + nq * 16 + lr8 + brsel;
                uint32_t off = (uint32_t)(nr * 80 + ks * 32 + bbsel);
                LDSM4(bh[nq], aBh + off);
                LDSM4(bl[nq], aBl + off);
            }
#pragma unroll
            for (int nq = 0; nq < 4; nq++) {
#pragma unroll
                for (int hf = 0; hf < 2; hf++) {
                    const int nt = nq * 2 + hf;
#pragma unroll
                    for (int mt = 0; mt < 4; mt++)
                        mma16816(c[mt][nt], ah[mt], bh[nq] + 2 * hf);
#pragma unroll
                    for (int mt = 0; mt < 4; mt++)
                        mma16816(c[mt][nt], ah[mt], bl[nq] + 2 * hf);
#pragma unroll
                    for (int mt = 0; mt < 4; mt++)
                        mma16816(c[mt][nt], al[mt], bh[nq] + 2 * hf);
                }
            }
        }
        __syncthreads();
    }

    // epilogue
    const int lq = lane >> 2;
    const int lr = lane & 3;
#pragma unroll
    for (int mt = 0; mt < 4; mt++) {
        const int rl0 = wm * 64 + mt * 16 + lq;      // local row
        const int rl1 = rl0 + 8;
        size_t r0 = rowA0 + rl0;
        size_t r1 = rowA0 + rl1;
        float p0[NOUT], p1[NOUT];
        if (MODE == 1) {
#pragma unroll
            for (int o = 0; o < NOUT; o++) { p0[o] = 0.0f; p1[o] = 0.0f; }
        }
#pragma unroll
        for (int nt = 0; nt < 8; nt++) {
            int nl = wn * 64 + nt * 8 + lr * 2;
            int ng = ncol0 + nl;
            float b0 = sBias[nl], b1 = sBias[nl + 1];
            float v00 = fmaxf(c[mt][nt][0] + b0, 0.0f);
            float v01 = fmaxf(c[mt][nt][1] + b1, 0.0f);
            float v10 = fmaxf(c[mt][nt][2] + b0, 0.0f);
            float v11 = fmaxf(c[mt][nt][3] + b1, 0.0f);
            if (MODE == 0) {
                uint32_t lo0, lo1;
                uint32_t hi0 = pack_split_hi(v00, v01, lo0);
                uint32_t hi1 = pack_split_hi(v10, v11, lo1);
                *(uint32_t*)(outH + r0 * NHID + ng) = hi0;
                *(uint32_t*)(outL + r0 * NHID + ng) = lo0;
                *(uint32_t*)(outH + r1 * NHID + ng) = hi1;
                *(uint32_t*)(outL + r1 * NHID + ng) = lo1;
            } else {
#pragma unroll
                for (int o = 0; o < NOUT; o++) {
                    float w0 = sOutW[o * BN + nl];
                    float w1 = sOutW[o * BN + nl + 1];
                    p0[o] = fmaf(v00, w0, fmaf(v01, w1, p0[o]));
                    p1[o] = fmaf(v10, w0, fmaf(v11, w1, p1[o]));
                }
            }
        }
        if (MODE == 1) {
#pragma unroll
            for (int off = 1; off <= 2; off <<= 1)
#pragma unroll
                for (int o = 0; o < NOUT; o++) {
                    p0[o] += __shfl_xor_sync(0xFFFFFFFF, p0[o], off);
                    p1[o] += __shfl_xor_sync(0xFFFFFFFF, p1[o], off);
                }
            // wn=0 deposits, wn=1 combines: one global atomic per (row,o)/CTA
            if (wn == 0 && lr == 0) {
#pragma unroll
                for (int o = 0; o < NOUT; o++) {
                    sPart[rl0 * NOUT + o] = p0[o];
                    sPart[rl1 * NOUT + o] = p1[o];
                }
            }
            __syncthreads();
            if (wn == 1 && lr == 0) {
#pragma unroll
                for (int o = 0; o < NOUT; o++) {
                    atomicAdd(outO + r0 * NOUT + o, p0[o] + sPart[rl0 * NOUT + o]);
                    atomicAdd(outO + r1 * NOUT + o, p1[o] + sPart[rl1 * NOUT + o]);
                }
            }
        }
    }
}

// ---------------------------------------------------------------------------
// Launch
// ---------------------------------------------------------------------------
extern "C" void kernel_launch(void* const* d_in, const int* in_sizes, int n_in,
                              void* d_out, int out_size) {
    const float* x      = (const float*)d_in[0];
    const float* conv_w = (const float*)d_in[1];
    const float* fc1_w  = (const float*)d_in[2];
    const float* fc1_b  = (const float*)d_in[3];
    const float* fc2_w  = (const float*)d_in[4];
    const float* fc2_b  = (const float*)d_in[5];
    const float* out_w  = (const float*)d_in[6];
    const float* out_b  = (const float*)d_in[7];
    float* out = (float*)d_out;

    __nv_bfloat16 *h0h, *h0l, *w1h, *w1l, *w2h, *w2l, *h1h, *h1l;
    cudaGetSymbolAddress((void**)&h0h, g_h0h);
    cudaGetSymbolAddress((void**)&h0l, g_h0l);
    cudaGetSymbolAddress((void**)&w1h, g_w1h);
    cudaGetSymbolAddress((void**)&w1l, g_w1l);
    cudaGetSymbolAddress((void**)&w2h, g_w2h);
    cudaGetSymbolAddress((void**)&w2l, g_w2l);
    cudaGetSymbolAddress((void**)&h1h, g_h1h);
    cudaGetSymbolAddress((void**)&h1l, g_h1l);

    prep_kernel<<<(PREP_END + CTHR - 1) / CTHR, CTHR>>>(fc1_w, fc2_w, out_b, out);
    conv_split_kernel<<<BROWS / CONV_IMGS, CTHR>>>(x, conv_w);
    {
        cudaFuncSetAttribute(gemm_kernel<0>,
                             cudaFuncAttributeMaxDynamicSharedMemorySize,
                             DSMEM_BYTES);
        dim3 grid(NHID / BN, BROWS / BM);
        gemm_kernel<0><<<grid, GTHR, DSMEM_BYTES>>>(
            h0h, h0l, w1h, w1l, fc1_b, K1PAD, h1h, h1l, nullptr, nullptr);
    }
    {
        cudaFuncSetAttribute(gemm_kernel<1>,
                             cudaFuncAttributeMaxDynamicSharedMemorySize,
                             DSMEM_BYTES);
        dim3 grid(NHID / BN, BROWS / BM);
        gemm_kernel<1><<<grid, GTHR, DSMEM_BYTES>>>(
            h1h, h1l, w2h, w2l, fc2_b, K2, nullptr, nullptr, out_w, out);
    }
}

// round 16
// speedup vs baseline: 2.1315x; 1.1962x over previous
#include <cuda_runtime.h>
#include <cuda_fp16.h>
#include <cstdint>

// ---------------------------------------------------------------------------
// DigitConvolutionalModel via warp-level mma.sync. R16: fp16 2-pass split —
// A = Ah + Al (fp16 pair, exact to ~2^-22), B rounded to single fp16.
// result = (Ah + Al) @ Bh^T; error = A @ (B - Bh) ~ 2^-12 relative (norm).
// 33% fewer MMAs than the bf16 3-pass scheme; B-lo arrays eliminated.
// Pipeline: prep (w->fp16, out=bias) ; conv->h0 fp16 hi/lo ;
//           gemm<0> h1 = relu(h0@w1^T+b1) -> fp16 hi/lo ;
//           gemm<1> h2 = relu(h1@w2^T+b2), fused out-layer atomics.
// ---------------------------------------------------------------------------

#define BROWS  32768
#define K1RAW  676
#define K1PAD  704          // 22 * 32
#define K2     512
#define NHID   512
#define NOUT   10
#define CTHR   256

#define BM 128
#define BN 128
#define BK 32
#define GTHR 128            // 4 warps: 2 (m) x 2 (n); warp tile 64 x 64

// dynamic smem layout (u32 units); row stride 80 B (64 B data + 16 pad)
#define ST_A_H   0
#define ST_A_L   2560
#define ST_B_H   5120
#define ST_SIZE  7680               // one stage = 30720 B
#define ST_BIAS  (2 * ST_SIZE)      // float[128]
#define ST_OUTW  (ST_BIAS + 128)    // float[10][128]
#define ST_PART  (ST_OUTW + 1280)   // float[128][10]
#define DSMEM_BYTES ((2 * ST_SIZE + 128 + 1280 + 1280) * 4 + 256)

// ---- scratch ---------------------------------------------------------------
__device__ __align__(16) __half g_h0h[(size_t)BROWS * K1PAD];
__device__ __align__(16) __half g_h0l[(size_t)BROWS * K1PAD];
__device__ __align__(16) __half g_w1h[(size_t)NHID * K1PAD];
__device__ __align__(16) __half g_w2h[(size_t)NHID * K2];
__device__ __align__(16) __half g_h1h[(size_t)BROWS * K2];
__device__ __align__(16) __half g_h1l[(size_t)BROWS * K2];

// ---- helpers ---------------------------------------------------------------
__device__ __forceinline__ void split_f16(float x, uint16_t& h, uint16_t& l) {
    __half hh = __float2half_rn(x);
    __half ll = __float2half_rn(x - __half2float(hh));
    h = __half_as_ushort(hh);
    l = __half_as_ushort(ll);
}
__device__ __forceinline__ uint32_t pack_split_hi(float a, float b,
                                                  uint32_t& lo_pack) {
    uint16_t ha, la, hb, lb;
    split_f16(a, ha, la);
    split_f16(b, hb, lb);
    lo_pack = (uint32_t)la | ((uint32_t)lb << 16);
    return (uint32_t)ha | ((uint32_t)hb << 16);
}

__device__ __forceinline__ void mma16816(float* c, const uint32_t* a,
                                         const uint32_t* b) {
    asm volatile(
        "mma.sync.aligned.m16n8k16.row.col.f32.f16.f16.f32 "
        "{%0,%1,%2,%3}, {%4,%5,%6,%7}, {%8,%9}, {%0,%1,%2,%3};"
        : "+f"(c[0]), "+f"(c[1]), "+f"(c[2]), "+f"(c[3])
        : "r"(a[0]), "r"(a[1]), "r"(a[2]), "r"(a[3]), "r"(b[0]), "r"(b[1]));
}
#define LDSM4(r, addr) \
    asm volatile("ldmatrix.sync.aligned.m8n8.x4.shared.b16 {%0,%1,%2,%3}, [%4];" \
        : "=r"((r)[0]), "=r"((r)[1]), "=r"((r)[2]), "=r"((r)[3]) : "r"(addr))
__device__ __forceinline__ void cp16(uint32_t saddr, const void* gaddr) {
    asm volatile("cp.async.cg.shared.global [%0], [%1], 16;"
                 :: "r"(saddr), "l"(gaddr));
}
#define CP_COMMIT() asm volatile("cp.async.commit_group;" ::: "memory")
#define CP_WAIT(n)  asm volatile("cp.async.wait_group %0;" :: "n"(n) : "memory")

// ---------------------------------------------------------------------------
// conv + split: 16 images per CTA; exact 22-iter task loop (5632 = 256*22).
// ---------------------------------------------------------------------------
#define CONV_IMGS 16
#define PAIRS_PER_IMG (K1PAD / 2)   // 352
__global__ void __launch_bounds__(CTHR)
conv_split_kernel(const float* __restrict__ x,
                  const float* __restrict__ w) {
    __shared__ float sx[CONV_IMGS * 784];
    __shared__ float sw[9];
    int tid = threadIdx.x;
    if (tid < 9) sw[tid] = w[tid];

    const float4* src = (const float4*)(x + (size_t)blockIdx.x * CONV_IMGS * 784);
    float4* dst = (float4*)sx;
#pragma unroll
    for (int it = 0; it < 13; it++) {
        int idx = tid + it * CTHR;
        if (idx < CONV_IMGS * 196) dst[idx] = src[idx];
    }
    __syncthreads();

    const size_t pairbase = (size_t)blockIdx.x * CONV_IMGS * PAIRS_PER_IMG;
#pragma unroll
    for (int it = 0; it < 22; it++) {
        int task = tid + it * CTHR;
        int img = task / PAIRS_PER_IMG;
        int pp = task - img * PAIRS_PER_IMG;
        int p0 = pp * 2;
        const float* sxi = sx + img * 784;

        float s[2] = {0.0f, 0.0f};
#pragma unroll
        for (int u = 0; u < 2; u++) {
            int p = p0 + u;
            if (p < K1RAW) {
                int i = p / 26, j = p - i * 26;
                const float* xb = sxi + i * 28 + j;
                float acc = 0.0f;
#pragma unroll
                for (int di = 0; di < 3; di++)
#pragma unroll
                    for (int dj = 0; dj < 3; dj++)
                        acc = fmaf(xb[di * 28 + dj], sw[di * 3 + dj], acc);
                s[u] = acc;
            }
        }
        uint32_t lo;
        uint32_t hi = pack_split_hi(s[0], s[1], lo);
        ((uint32_t*)g_h0h)[pairbase + task] = hi;
        ((uint32_t*)g_h0l)[pairbase + task] = lo;
    }
}

// ---------------------------------------------------------------------------
// merged prep: w1 -> fp16 (pad), w2 -> fp16, out init.
// ---------------------------------------------------------------------------
#define PREP_W1  (NHID * K1PAD)                 // 360448
#define PREP_W2  (PREP_W1 + NHID * K2)          // 622592
#define PREP_END (PREP_W2 + BROWS * NOUT)       // 950272
__global__ void prep_kernel(const float* __restrict__ w1,
                            const float* __restrict__ w2,
                            const float* __restrict__ out_b,
                            float* __restrict__ out) {
    int idx = blockIdx.x * blockDim.x + threadIdx.x;
    if (idx < PREP_W1) {
        int n = idx / K1PAD, k = idx - n * K1PAD;
        float v = (k < K1RAW) ? w1[n * K1RAW + k] : 0.0f;
        g_w1h[idx] = __float2half_rn(v);
    } else if (idx < PREP_W2) {
        int j = idx - PREP_W1;
        g_w2h[j] = __float2half_rn(w2[j]);
    } else if (idx < PREP_END) {
        int j = idx - PREP_W2;
        out[j] = out_b[j % NOUT];
    }
}

// ---------------------------------------------------------------------------
// Tiled GEMM, fp16 2-pass (Ah*Bh + Al*Bh), 4 warps of 64x64.
// MODE 0: out = relu(C + bias) split -> (outH, outL) fp16
// MODE 1: v = relu(C + bias); out-layer partials combined in smem, one
//         atomicAdd per (row, o) per CTA.
// ---------------------------------------------------------------------------
template <int MODE>
__global__ void __launch_bounds__(GTHR, 2)
gemm_kernel(const __half* __restrict__ Ah,
            const __half* __restrict__ Al,
            const __half* __restrict__ Wh,
            const float* __restrict__ bias, int K,
            __half* __restrict__ outH,
            __half* __restrict__ outL,
            const float* __restrict__ outW,
            float* __restrict__ outO) {
    extern __shared__ uint32_t dsm[];
    float* sBias = (float*)(dsm + ST_BIAS);
    float* sOutW = (float*)(dsm + ST_OUTW);
    float* sPart = (float*)(dsm + ST_PART);
    const uint32_t sbase = (uint32_t)__cvta_generic_to_shared(dsm);

    const int tid = threadIdx.x;
    const int lane = tid & 31;
    const int warp = tid >> 5;
    const int wm = warp & 1;
    const int wn = warp >> 1;
    const size_t rowA0 = (size_t)blockIdx.y * BM;
    const int ncol0 = blockIdx.x * BN;

    if (tid < BN) sBias[tid] = bias[ncol0 + tid];
    if (MODE == 1) {
#pragma unroll
        for (int it = 0; it < 10; it++) {
            int i = tid + it * GTHR;
            int o = i >> 7, j = i & 127;
            sOutW[o * BN + j] = outW[o * NHID + ncol0 + j];
        }
    }

    float c[4][8][4];
#pragma unroll
    for (int mt = 0; mt < 4; mt++)
#pragma unroll
        for (int nt = 0; nt < 8; nt++)
#pragma unroll
            for (int i = 0; i < 4; i++) c[mt][nt][i] = 0.0f;

    const int kcn = K / BK;

    auto stage = [&](int kc, int s) {
        uint32_t sb = sbase + (uint32_t)(s * ST_SIZE * 4);
#pragma unroll
        for (int it = 0; it < 4; it++) {
            int i = tid + it * GTHR;
            int row = i >> 2, quad = i & 3;
            uint32_t soff = (uint32_t)(row * 80 + quad * 16);
            size_t ga = (rowA0 + row) * (size_t)K + kc * BK + quad * 8;
            size_t gb = (size_t)(ncol0 + row) * K + kc * BK + quad * 8;
            cp16(sb + ST_A_H * 4 + soff, Ah + ga);
            cp16(sb + ST_A_L * 4 + soff, Al + ga);
            cp16(sb + ST_B_H * 4 + soff, Wh + gb);
        }
    };

    stage(0, 0);
    CP_COMMIT();

    const int g = lane >> 3, lr8 = lane & 7;
    const int arsel = (g & 1) ? 8 : 0;
    const int absel = (g & 2) ? 16 : 0;
    const int brsel = (g & 2) ? 8 : 0;
    const int bbsel = (g & 1) ? 16 : 0;

    for (int kc = 0; kc < kcn; kc++) {
        if (kc + 1 < kcn) {
            stage(kc + 1, (kc + 1) & 1);
            CP_COMMIT();
            CP_WAIT(1);
        } else {
            CP_WAIT(0);
        }
        __syncthreads();

        const uint32_t sb = sbase + (uint32_t)((kc & 1) * ST_SIZE * 4);
        const uint32_t aAh = sb + ST_A_H * 4;
        const uint32_t aAl = sb + ST_A_L * 4;
        const uint32_t aBh = sb + ST_B_H * 4;

#pragma unroll
        for (int ks = 0; ks < 2; ks++) {
            uint32_t ah[4][4], al[4][4];
#pragma unroll
            for (int mt = 0; mt < 4; mt++) {
                int r = wm * 64 + mt * 16 + lr8 + arsel;
                uint32_t off = (uint32_t)(r * 80 + ks * 32 + absel);
                LDSM4(ah[mt], aAh + off);
                LDSM4(al[mt], aAl + off);
            }
            uint32_t bh[4][4];
#pragma unroll
            for (int nq = 0; nq < 4; nq++) {
                int nr = wn * 64 + nq * 16 + lr8 + brsel;
                uint32_t off = (uint32_t)(nr * 80 + ks * 32 + bbsel);
                LDSM4(bh[nq], aBh + off);
            }
#pragma unroll
            for (int nq = 0; nq < 4; nq++) {
#pragma unroll
                for (int hf = 0; hf < 2; hf++) {
                    const int nt = nq * 2 + hf;
                    // per-acc order: hh then lh
#pragma unroll
                    for (int mt = 0; mt < 4; mt++)
                        mma16816(c[mt][nt], ah[mt], bh[nq] + 2 * hf);
#pragma unroll
                    for (int mt = 0; mt < 4; mt++)
                        mma16816(c[mt][nt], al[mt], bh[nq] + 2 * hf);
                }
            }
        }
        __syncthreads();
    }

    // epilogue
    const int lq = lane >> 2;
    const int lr = lane & 3;
#pragma unroll
    for (int mt = 0; mt < 4; mt++) {
        const int rl0 = wm * 64 + mt * 16 + lq;
        const int rl1 = rl0 + 8;
        size_t r0 = rowA0 + rl0;
        size_t r1 = rowA0 + rl1;
        float p0[NOUT], p1[NOUT];
        if (MODE == 1) {
#pragma unroll
            for (int o = 0; o < NOUT; o++) { p0[o] = 0.0f; p1[o] = 0.0f; }
        }
#pragma unroll
        for (int nt = 0; nt < 8; nt++) {
            int nl = wn * 64 + nt * 8 + lr * 2;
            int ng = ncol0 + nl;
            float b0 = sBias[nl], b1 = sBias[nl + 1];
            float v00 = fmaxf(c[mt][nt][0] + b0, 0.0f);
            float v01 = fmaxf(c[mt][nt][1] + b1, 0.0f);
            float v10 = fmaxf(c[mt][nt][2] + b0, 0.0f);
            float v11 = fmaxf(c[mt][nt][3] + b1, 0.0f);
            if (MODE == 0) {
                uint32_t lo0, lo1;
                uint32_t hi0 = pack_split_hi(v00, v01, lo0);
                uint32_t hi1 = pack_split_hi(v10, v11, lo1);
                *(uint32_t*)(outH + r0 * NHID + ng) = hi0;
                *(uint32_t*)(outL + r0 * NHID + ng) = lo0;
                *(uint32_t*)(outH + r1 * NHID + ng) = hi1;
                *(uint32_t*)(outL + r1 * NHID + ng) = lo1;
            } else {
#pragma unroll
                for (int o = 0; o < NOUT; o++) {
                    float w0 = sOutW[o * BN + nl];
                    float w1 = sOutW[o * BN + nl + 1];
                    p0[o] = fmaf(v00, w0, fmaf(v01, w1, p0[o]));
                    p1[o] = fmaf(v10, w0, fmaf(v11, w1, p1[o]));
                }
            }
        }
        if (MODE == 1) {
#pragma unroll
            for (int off = 1; off <= 2; off <<= 1)
#pragma unroll
                for (int o = 0; o < NOUT; o++) {
                    p0[o] += __shfl_xor_sync(0xFFFFFFFF, p0[o], off);
                    p1[o] += __shfl_xor_sync(0xFFFFFFFF, p1[o], off);
                }
            if (wn == 0 && lr == 0) {
#pragma unroll
                for (int o = 0; o < NOUT; o++) {
                    sPart[rl0 * NOUT + o] = p0[o];
                    sPart[rl1 * NOUT + o] = p1[o];
                }
            }
            __syncthreads();
            if (wn == 1 && lr == 0) {
#pragma unroll
                for (int o = 0; o < NOUT; o++) {
                    atomicAdd(outO + r0 * NOUT + o, p0[o] + sPart[rl0 * NOUT + o]);
                    atomicAdd(outO + r1 * NOUT + o, p1[o] + sPart[rl1 * NOUT + o]);
                }
            }
        }
    }
}

// ---------------------------------------------------------------------------
// Launch
// ---------------------------------------------------------------------------
extern "C" void kernel_launch(void* const* d_in, const int* in_sizes, int n_in,
                              void* d_out, int out_size) {
    const float* x      = (const float*)d_in[0];
    const float* conv_w = (const float*)d_in[1];
    const float* fc1_w  = (const float*)d_in[2];
    const float* fc1_b  = (const float*)d_in[3];
    const float* fc2_w  = (const float*)d_in[4];
    const float* fc2_b  = (const float*)d_in[5];
    const float* out_w  = (const float*)d_in[6];
    const float* out_b  = (const float*)d_in[7];
    float* out = (float*)d_out;

    __half *h0h, *h0l, *w1h, *w2h, *h1h, *h1l;
    cudaGetSymbolAddress((void**)&h0h, g_h0h);
    cudaGetSymbolAddress((void**)&h0l, g_h0l);
    cudaGetSymbolAddress((void**)&w1h, g_w1h);
    cudaGetSymbolAddress((void**)&w2h, g_w2h);
    cudaGetSymbolAddress((void**)&h1h, g_h1h);
    cudaGetSymbolAddress((void**)&h1l, g_h1l);

    prep_kernel<<<(PREP_END + CTHR - 1) / CTHR, CTHR>>>(fc1_w, fc2_w, out_b, out);
    conv_split_kernel<<<BROWS / CONV_IMGS, CTHR>>>(x, conv_w);
    {
        cudaFuncSetAttribute(gemm_kernel<0>,
                             cudaFuncAttributeMaxDynamicSharedMemorySize,
                             DSMEM_BYTES);
        dim3 grid(NHID / BN, BROWS / BM);
        gemm_kernel<0><<<grid, GTHR, DSMEM_BYTES>>>(
            h0h, h0l, w1h, fc1_b, K1PAD, h1h, h1l, nullptr, nullptr);
    }
    {
        cudaFuncSetAttribute(gemm_kernel<1>,
                             cudaFuncAttributeMaxDynamicSharedMemorySize,
                             DSMEM_BYTES);
        dim3 grid(NHID / BN, BROWS / BM);
        gemm_kernel<1><<<grid, GTHR, DSMEM_BYTES>>>(
            h1h, h1l, w2h, fc2_b, K2, nullptr, nullptr, out_w, out);
    }
}

// round 17
// speedup vs baseline: 2.2533x; 1.0571x over previous
#include <cuda_runtime.h>
#include <cuda_fp16.h>
#include <cstdint>

// ---------------------------------------------------------------------------
// DigitConvolutionalModel via warp-level mma.sync. R17: fp16 2-pass split
// (A = Ah+Al fp16 pair, B fp16-rounded; result = A@Bh), 3-stage cp.async
// ring w/ prefetch distance 2 and a single __syncthreads per k-chunk,
// conv+prep merged into one front kernel.
// ---------------------------------------------------------------------------

#define BROWS  32768
#define K1RAW  676
#define K1PAD  704          // 22 * 32
#define K2     512
#define NHID   512
#define NOUT   10
#define CTHR   256

#define BM 128
#define BN 128
#define BK 32
#define GTHR 128            // 4 warps: 2 (m) x 2 (n); warp tile 64 x 64

// dynamic smem layout (u32 units); row stride 80 B
#define ST_A_H   0
#define ST_A_L   2560
#define ST_B_H   5120
#define ST_SIZE  7680               // one stage = 30720 B
#define ST_BIAS  (3 * ST_SIZE)      // float[128]
#define ST_OUTW  (ST_BIAS + 128)    // float[10][128]
#define ST_PART  (ST_OUTW + 1280)   // float[128][10]
#define DSMEM_BYTES ((3 * ST_SIZE + 128 + 1280 + 1280) * 4 + 256)  // ~103 KB

// ---- scratch ---------------------------------------------------------------
__device__ __align__(16) __half g_h0h[(size_t)BROWS * K1PAD];
__device__ __align__(16) __half g_h0l[(size_t)BROWS * K1PAD];
__device__ __align__(16) __half g_w1h[(size_t)NHID * K1PAD];
__device__ __align__(16) __half g_w2h[(size_t)NHID * K2];
__device__ __align__(16) __half g_h1h[(size_t)BROWS * K2];
__device__ __align__(16) __half g_h1l[(size_t)BROWS * K2];

// ---- helpers ---------------------------------------------------------------
__device__ __forceinline__ void split_f16(float x, uint16_t& h, uint16_t& l) {
    __half hh = __float2half_rn(x);
    __half ll = __float2half_rn(x - __half2float(hh));
    h = __half_as_ushort(hh);
    l = __half_as_ushort(ll);
}
__device__ __forceinline__ uint32_t pack_split_hi(float a, float b,
                                                  uint32_t& lo_pack) {
    uint16_t ha, la, hb, lb;
    split_f16(a, ha, la);
    split_f16(b, hb, lb);
    lo_pack = (uint32_t)la | ((uint32_t)lb << 16);
    return (uint32_t)ha | ((uint32_t)hb << 16);
}

__device__ __forceinline__ void mma16816(float* c, const uint32_t* a,
                                         const uint32_t* b) {
    asm volatile(
        "mma.sync.aligned.m16n8k16.row.col.f32.f16.f16.f32 "
        "{%0,%1,%2,%3}, {%4,%5,%6,%7}, {%8,%9}, {%0,%1,%2,%3};"
        : "+f"(c[0]), "+f"(c[1]), "+f"(c[2]), "+f"(c[3])
        : "r"(a[0]), "r"(a[1]), "r"(a[2]), "r"(a[3]), "r"(b[0]), "r"(b[1]));
}
#define LDSM4(r, addr) \
    asm volatile("ldmatrix.sync.aligned.m8n8.x4.shared.b16 {%0,%1,%2,%3}, [%4];" \
        : "=r"((r)[0]), "=r"((r)[1]), "=r"((r)[2]), "=r"((r)[3]) : "r"(addr))
__device__ __forceinline__ void cp16(uint32_t saddr, const void* gaddr) {
    asm volatile("cp.async.cg.shared.global [%0], [%1], 16;"
                 :: "r"(saddr), "l"(gaddr));
}
#define CP_COMMIT() asm volatile("cp.async.commit_group;" ::: "memory")
#define CP_WAIT(n)  asm volatile("cp.async.wait_group %0;" :: "n"(n) : "memory")

// ---------------------------------------------------------------------------
// front kernel: blocks [0, CONV_BLOCKS) do conv+split; rest do weight
// split + out init. One launch; work overlaps across SMs.
// ---------------------------------------------------------------------------
#define CONV_IMGS 16
#define PAIRS_PER_IMG (K1PAD / 2)   // 352
#define CONV_BLOCKS (BROWS / CONV_IMGS)          // 2048
#define PREP_W1  (NHID * K1PAD)                  // 360448
#define PREP_W2  (PREP_W1 + NHID * K2)           // 622592
#define PREP_END (PREP_W2 + BROWS * NOUT)        // 950272
#define PREP_BLOCKS ((PREP_END + CTHR - 1) / CTHR)
#define FRONT_BLOCKS (CONV_BLOCKS + PREP_BLOCKS)

__global__ void __launch_bounds__(CTHR)
front_kernel(const float* __restrict__ x,
             const float* __restrict__ w,
             const float* __restrict__ w1,
             const float* __restrict__ w2,
             const float* __restrict__ out_b,
             float* __restrict__ out) {
    __shared__ float sx[CONV_IMGS * 784];
    __shared__ float sw[9];
    int tid = threadIdx.x;

    if (blockIdx.x < CONV_BLOCKS) {
        if (tid < 9) sw[tid] = w[tid];
        const float4* src =
            (const float4*)(x + (size_t)blockIdx.x * CONV_IMGS * 784);
        float4* dst = (float4*)sx;
#pragma unroll
        for (int it = 0; it < 13; it++) {
            int idx = tid + it * CTHR;
            if (idx < CONV_IMGS * 196) dst[idx] = src[idx];
        }
        __syncthreads();

        const size_t pairbase = (size_t)blockIdx.x * CONV_IMGS * PAIRS_PER_IMG;
#pragma unroll
        for (int it = 0; it < 22; it++) {
            int task = tid + it * CTHR;
            int img = task / PAIRS_PER_IMG;
            int pp = task - img * PAIRS_PER_IMG;
            int p0 = pp * 2;
            const float* sxi = sx + img * 784;

            float s[2] = {0.0f, 0.0f};
#pragma unroll
            for (int u = 0; u < 2; u++) {
                int p = p0 + u;
                if (p < K1RAW) {
                    int i = p / 26, j = p - i * 26;
                    const float* xb = sxi + i * 28 + j;
                    float acc = 0.0f;
#pragma unroll
                    for (int di = 0; di < 3; di++)
#pragma unroll
                        for (int dj = 0; dj < 3; dj++)
                            acc = fmaf(xb[di * 28 + dj], sw[di * 3 + dj], acc);
                    s[u] = acc;
                }
            }
            uint32_t lo;
            uint32_t hi = pack_split_hi(s[0], s[1], lo);
            ((uint32_t*)g_h0h)[pairbase + task] = hi;
            ((uint32_t*)g_h0l)[pairbase + task] = lo;
        }
    } else {
        int idx = (blockIdx.x - CONV_BLOCKS) * CTHR + tid;
        if (idx < PREP_W1) {
            int n = idx / K1PAD, k = idx - n * K1PAD;
            float v = (k < K1RAW) ? w1[n * K1RAW + k] : 0.0f;
            g_w1h[idx] = __float2half_rn(v);
        } else if (idx < PREP_W2) {
            int j = idx - PREP_W1;
            g_w2h[j] = __float2half_rn(w2[j]);
        } else if (idx < PREP_END) {
            int j = idx - PREP_W2;
            out[j] = out_b[j % NOUT];
        }
    }
}

// ---------------------------------------------------------------------------
// Tiled GEMM, fp16 2-pass, 4 warps of 64x64, 3-stage ring, 1 sync/chunk.
// MODE 0: out = relu(C + bias) split -> (outH, outL) fp16
// MODE 1: v = relu(C + bias); fused out-layer, one atomic per (row,o)/CTA.
// ---------------------------------------------------------------------------
template <int MODE>
__global__ void __launch_bounds__(GTHR, 2)
gemm_kernel(const __half* __restrict__ Ah,
            const __half* __restrict__ Al,
            const __half* __restrict__ Wh,
            const float* __restrict__ bias, int K,
            __half* __restrict__ outH,
            __half* __restrict__ outL,
            const float* __restrict__ outW,
            float* __restrict__ outO) {
    extern __shared__ uint32_t dsm[];
    float* sBias = (float*)(dsm + ST_BIAS);
    float* sOutW = (float*)(dsm + ST_OUTW);
    float* sPart = (float*)(dsm + ST_PART);
    const uint32_t sbase = (uint32_t)__cvta_generic_to_shared(dsm);

    const int tid = threadIdx.x;
    const int lane = tid & 31;
    const int warp = tid >> 5;
    const int wm = warp & 1;
    const int wn = warp >> 1;
    const size_t rowA0 = (size_t)blockIdx.y * BM;
    const int ncol0 = blockIdx.x * BN;

    if (tid < BN) sBias[tid] = bias[ncol0 + tid];
    if (MODE == 1) {
#pragma unroll
        for (int it = 0; it < 10; it++) {
            int i = tid + it * GTHR;
            int o = i >> 7, j = i & 127;
            sOutW[o * BN + j] = outW[o * NHID + ncol0 + j];
        }
    }

    float c[4][8][4];
#pragma unroll
    for (int mt = 0; mt < 4; mt++)
#pragma unroll
        for (int nt = 0; nt < 8; nt++)
#pragma unroll
            for (int i = 0; i < 4; i++) c[mt][nt][i] = 0.0f;

    const int kcn = K / BK;

    auto stage = [&](int kc, int s) {
        uint32_t sb = sbase + (uint32_t)(s * ST_SIZE * 4);
#pragma unroll
        for (int it = 0; it < 4; it++) {
            int i = tid + it * GTHR;
            int row = i >> 2, quad = i & 3;
            uint32_t soff = (uint32_t)(row * 80 + quad * 16);
            size_t ga = (rowA0 + row) * (size_t)K + kc * BK + quad * 8;
            size_t gb = (size_t)(ncol0 + row) * K + kc * BK + quad * 8;
            cp16(sb + ST_A_H * 4 + soff, Ah + ga);
            cp16(sb + ST_A_L * 4 + soff, Al + ga);
            cp16(sb + ST_B_H * 4 + soff, Wh + gb);
        }
    };

    stage(0, 0);
    CP_COMMIT();
    stage(1, 1);
    CP_COMMIT();

    const int g = lane >> 3, lr8 = lane & 7;
    const int arsel = (g & 1) ? 8 : 0;
    const int absel = (g & 2) ? 16 : 0;
    const int brsel = (g & 2) ? 8 : 0;
    const int bbsel = (g & 1) ? 16 : 0;

    for (int kc = 0; kc < kcn; kc++) {
        if (kc + 1 < kcn) { CP_WAIT(1); } else { CP_WAIT(0); }
        __syncthreads();   // stage kc visible; all done with chunk kc-1
        if (kc + 2 < kcn) {
            stage(kc + 2, (kc + 2) % 3);   // overwrites buffer (kc-1)%3: safe
            CP_COMMIT();
        }

        const uint32_t sb = sbase + (uint32_t)((kc % 3) * ST_SIZE * 4);
        const uint32_t aAh = sb + ST_A_H * 4;
        const uint32_t aAl = sb + ST_A_L * 4;
        const uint32_t aBh = sb + ST_B_H * 4;

#pragma unroll
        for (int ks = 0; ks < 2; ks++) {
            uint32_t ah[4][4], al[4][4];
#pragma unroll
            for (int mt = 0; mt < 4; mt++) {
                int r = wm * 64 + mt * 16 + lr8 + arsel;
                uint32_t off = (uint32_t)(r * 80 + ks * 32 + absel);
                LDSM4(ah[mt], aAh + off);
                LDSM4(al[mt], aAl + off);
            }
            uint32_t bh[4][4];
#pragma unroll
            for (int nq = 0; nq < 4; nq++) {
                int nr = wn * 64 + nq * 16 + lr8 + brsel;
                uint32_t off = (uint32_t)(nr * 80 + ks * 32 + bbsel);
                LDSM4(bh[nq], aBh + off);
            }
#pragma unroll
            for (int nq = 0; nq < 4; nq++) {
#pragma unroll
                for (int hf = 0; hf < 2; hf++) {
                    const int nt = nq * 2 + hf;
#pragma unroll
                    for (int mt = 0; mt < 4; mt++)
                        mma16816(c[mt][nt], ah[mt], bh[nq] + 2 * hf);
#pragma unroll
                    for (int mt = 0; mt < 4; mt++)
                        mma16816(c[mt][nt], al[mt], bh[nq] + 2 * hf);
                }
            }
        }
    }
    __syncthreads();   // mainloop reads done before epilogue smem reuse

    // epilogue
    const int lq = lane >> 2;
    const int lr = lane & 3;
#pragma unroll
    for (int mt = 0; mt < 4; mt++) {
        const int rl0 = wm * 64 + mt * 16 + lq;
        const int rl1 = rl0 + 8;
        size_t r0 = rowA0 + rl0;
        size_t r1 = rowA0 + rl1;
        float p0[NOUT], p1[NOUT];
        if (MODE == 1) {
#pragma unroll
            for (int o = 0; o < NOUT; o++) { p0[o] = 0.0f; p1[o] = 0.0f; }
        }
#pragma unroll
        for (int nt = 0; nt < 8; nt++) {
            int nl = wn * 64 + nt * 8 + lr * 2;
            int ng = ncol0 + nl;
            float b0 = sBias[nl], b1 = sBias[nl + 1];
            float v00 = fmaxf(c[mt][nt][0] + b0, 0.0f);
            float v01 = fmaxf(c[mt][nt][1] + b1, 0.0f);
            float v10 = fmaxf(c[mt][nt][2] + b0, 0.0f);
            float v11 = fmaxf(c[mt][nt][3] + b1, 0.0f);
            if (MODE == 0) {
                uint32_t lo0, lo1;
                uint32_t hi0 = pack_split_hi(v00, v01, lo0);
                uint32_t hi1 = pack_split_hi(v10, v11, lo1);
                *(uint32_t*)(outH + r0 * NHID + ng) = hi0;
                *(uint32_t*)(outL + r0 * NHID + ng) = lo0;
                *(uint32_t*)(outH + r1 * NHID + ng) = hi1;
                *(uint32_t*)(outL + r1 * NHID + ng) = lo1;
            } else {
#pragma unroll
                for (int o = 0; o < NOUT; o++) {
                    float w0 = sOutW[o * BN + nl];
                    float w1 = sOutW[o * BN + nl + 1];
                    p0[o] = fmaf(v00, w0, fmaf(v01, w1, p0[o]));
                    p1[o] = fmaf(v10, w0, fmaf(v11, w1, p1[o]));
                }
            }
        }
        if (MODE == 1) {
#pragma unroll
            for (int off = 1; off <= 2; off <<= 1)
#pragma unroll
                for (int o = 0; o < NOUT; o++) {
                    p0[o] += __shfl_xor_sync(0xFFFFFFFF, p0[o], off);
                    p1[o] += __shfl_xor_sync(0xFFFFFFFF, p1[o], off);
                }
            if (wn == 0 && lr == 0) {
#pragma unroll
                for (int o = 0; o < NOUT; o++) {
                    sPart[rl0 * NOUT + o] = p0[o];
                    sPart[rl1 * NOUT + o] = p1[o];
                }
            }
            __syncthreads();
            if (wn == 1 && lr == 0) {
#pragma unroll
                for (int o = 0; o < NOUT; o++) {
                    atomicAdd(outO + r0 * NOUT + o, p0[o] + sPart[rl0 * NOUT + o]);
                    atomicAdd(outO + r1 * NOUT + o, p1[o] + sPart[rl1 * NOUT + o]);
                }
            }
        }
    }
}

// ---------------------------------------------------------------------------
// Launch
// ---------------------------------------------------------------------------
extern "C" void kernel_launch(void* const* d_in, const int* in_sizes, int n_in,
                              void* d_out, int out_size) {
    const float* x      = (const float*)d_in[0];
    const float* conv_w = (const float*)d_in[1];
    const float* fc1_w  = (const float*)d_in[2];
    const float* fc1_b  = (const float*)d_in[3];
    const float* fc2_w  = (const float*)d_in[4];
    const float* fc2_b  = (const float*)d_in[5];
    const float* out_w  = (const float*)d_in[6];
    const float* out_b  = (const float*)d_in[7];
    float* out = (float*)d_out;

    __half *h0h, *h0l, *w1h, *w2h, *h1h, *h1l;
    cudaGetSymbolAddress((void**)&h0h, g_h0h);
    cudaGetSymbolAddress((void**)&h0l, g_h0l);
    cudaGetSymbolAddress((void**)&w1h, g_w1h);
    cudaGetSymbolAddress((void**)&w2h, g_w2h);
    cudaGetSymbolAddress((void**)&h1h, g_h1h);
    cudaGetSymbolAddress((void**)&h1l, g_h1l);

    front_kernel<<<FRONT_BLOCKS, CTHR>>>(x, conv_w, fc1_w, fc2_w, out_b, out);
    {
        cudaFuncSetAttribute(gemm_kernel<0>,
                             cudaFuncAttributeMaxDynamicSharedMemorySize,
                             DSMEM_BYTES);
        dim3 grid(NHID / BN, BROWS / BM);
        gemm_kernel<0><<<grid, GTHR, DSMEM_BYTES>>>(
            h0h, h0l, w1h, fc1_b, K1PAD, h1h, h1l, nullptr, nullptr);
    }
    {
        cudaFuncSetAttribute(gemm_kernel<1>,
                             cudaFuncAttributeMaxDynamicSharedMemorySize,
                             DSMEM_BYTES);
        dim3 grid(NHID / BN, BROWS / BM);
        gemm_kernel<1><<<grid, GTHR, DSMEM_BYTES>>>(
            h1h, h1l, w2h, fc2_b, K2, nullptr, nullptr, out_w, out);
    }
}